// round 1
// baseline (speedup 1.0000x reference)
#include <cuda_runtime.h>

#define Bq 8
#define Tq 2048
#define Dq 1024
#define Hq 64
#define BT (Bq*Tq)

// scratch for projected q,k,v  (12 MB total, static device globals: allowed)
__device__ float g_q[BT*Hq];
__device__ float g_k[BT*Hq];
__device__ float g_v[BT*Hq];

// ---------------------------------------------------------------------------
// Kernel 1: fused QKV projection.
// grid = 256 blocks (64 rows of x each), 256 threads.
// Thread (ty,tx) computes 4 rows x 4 cols for each of Wq/Wk/Wv.
// ---------------------------------------------------------------------------
__global__ __launch_bounds__(256) void qkv_proj_kernel(
    const float* __restrict__ x,
    const float* __restrict__ Wq,
    const float* __restrict__ Wk,
    const float* __restrict__ Wv)
{
    __shared__ float Xst[16*68];    // x chunk transposed: [c][r], stride 68
    __shared__ float Ws[3*16*64];   // W chunks: [w][kc][h]

    const int tid = threadIdx.x;
    const int tx  = tid & 15;
    const int ty  = tid >> 4;
    const int row0 = blockIdx.x * 64;

    float acc[3][4][4];
    #pragma unroll
    for (int w = 0; w < 3; ++w)
        #pragma unroll
        for (int i = 0; i < 4; ++i)
            #pragma unroll
            for (int j = 0; j < 4; ++j)
                acc[w][i][j] = 0.0f;

    for (int kc = 0; kc < Dq; kc += 16) {
        __syncthreads();
        // load x chunk (64 rows x 16 cols), transposed into smem
        #pragma unroll
        for (int i = tid; i < 64*16; i += 256) {
            int r = i >> 4, c = i & 15;
            Xst[c*68 + r] = x[(row0 + r)*Dq + kc + c];
        }
        // load weight chunks (3 x 16 x 64), row-major
        #pragma unroll
        for (int i = tid; i < 3*16*64; i += 256) {
            int w   = i >> 10;
            int rem = i & 1023;
            int r   = rem >> 6;
            int c   = rem & 63;
            const float* Wp = (w == 0) ? Wq : (w == 1) ? Wk : Wv;
            Ws[i] = Wp[(kc + r)*Hq + c];
        }
        __syncthreads();

        #pragma unroll
        for (int kk = 0; kk < 16; ++kk) {
            float4 xf = *(const float4*)&Xst[kk*68 + ty*4];
            float xv[4] = {xf.x, xf.y, xf.z, xf.w};
            #pragma unroll
            for (int w = 0; w < 3; ++w) {
                float4 wf = *(const float4*)&Ws[w*1024 + kk*64 + tx*4];
                float wv[4] = {wf.x, wf.y, wf.z, wf.w};
                #pragma unroll
                for (int i = 0; i < 4; ++i)
                    #pragma unroll
                    for (int j = 0; j < 4; ++j)
                        acc[w][i][j] += xv[i] * wv[j];
            }
        }
    }

    // write q,k,v scratch
    #pragma unroll
    for (int i = 0; i < 4; ++i) {
        int row = row0 + ty*4 + i;
        float4 oq = make_float4(acc[0][i][0], acc[0][i][1], acc[0][i][2], acc[0][i][3]);
        float4 ok = make_float4(acc[1][i][0], acc[1][i][1], acc[1][i][2], acc[1][i][3]);
        float4 ov = make_float4(acc[2][i][0], acc[2][i][1], acc[2][i][2], acc[2][i][3]);
        *(float4*)&g_q[row*Hq + tx*4] = oq;
        *(float4*)&g_k[row*Hq + tx*4] = ok;
        *(float4*)&g_v[row*Hq + tx*4] = ov;
    }
}

// ---------------------------------------------------------------------------
// Kernel 2: causal flash attention, fp32.
// grid = (32 query tiles, 8 batches), 256 threads, BM=BN=64.
// smem layouts (stride 68 pad, all float4 reads conflict-free/broadcast):
//   Qt[h][m], Kt[h][n]  (transposed),  Vs[n][h],  Ps[n][m]
// ---------------------------------------------------------------------------
#define ATTN_SMEM (4*68*64*4)

__global__ __launch_bounds__(256) void attn_kernel(float* __restrict__ out)
{
    extern __shared__ float sm[];
    float* Qt = sm;             // 68*64
    float* Kt = sm + 68*64;
    float* Vs = sm + 2*68*64;
    float* Ps = sm + 3*68*64;

    const int tid = threadIdx.x;
    const int tx  = tid & 15;
    const int ty  = tid >> 4;
    const int qt  = 31 - (int)blockIdx.x;   // heavy (long) blocks launch first
    const int b   = blockIdx.y;
    const int q0  = qt * 64;
    const int base_q = (b*Tq + q0) * Hq;

    // load Q tile, transposed: Qt[h][t]
    #pragma unroll
    for (int i = tid; i < 64*64; i += 256) {
        int t = i >> 6, h = i & 63;
        Qt[h*68 + t] = g_q[base_q + i];
    }

    float acc[4][4];
    #pragma unroll
    for (int i = 0; i < 4; ++i)
        #pragma unroll
        for (int j = 0; j < 4; ++j)
            acc[i][j] = 0.0f;

    float m_r[4] = {-1e30f, -1e30f, -1e30f, -1e30f};
    float l_r[4] = {0.0f, 0.0f, 0.0f, 0.0f};

    for (int kt = 0; kt <= qt; ++kt) {
        __syncthreads();   // previous PV done (and Q load done on first iter)

        const int base_k = (b*Tq + kt*64) * Hq;
        // K tile transposed: Kt[h][t]
        #pragma unroll
        for (int i = tid; i < 64*64; i += 256) {
            int t = i >> 6, h = i & 63;
            Kt[h*68 + t] = g_k[base_k + i];
        }
        // V tile row-major: Vs[t][h]
        const float4* gv4 = (const float4*)(g_v + base_k);
        #pragma unroll
        for (int i = tid; i < 64*16; i += 256) {
            int t = i >> 4, h4 = i & 15;
            *(float4*)&Vs[t*68 + h4*4] = gv4[i];
        }
        __syncthreads();

        // ---- S = (Q K^T) / sqrt(H) ----
        float s[4][4];
        #pragma unroll
        for (int i = 0; i < 4; ++i)
            #pragma unroll
            for (int j = 0; j < 4; ++j)
                s[i][j] = 0.0f;

        #pragma unroll 8
        for (int h = 0; h < 64; ++h) {
            float4 qf = *(const float4*)&Qt[h*68 + ty*4];
            float4 kf = *(const float4*)&Kt[h*68 + tx*4];
            float qv[4] = {qf.x, qf.y, qf.z, qf.w};
            float kv[4] = {kf.x, kf.y, kf.z, kf.w};
            #pragma unroll
            for (int i = 0; i < 4; ++i)
                #pragma unroll
                for (int j = 0; j < 4; ++j)
                    s[i][j] += qv[i] * kv[j];
        }

        const bool diag = (kt == qt);
        #pragma unroll
        for (int i = 0; i < 4; ++i)
            #pragma unroll
            for (int j = 0; j < 4; ++j) {
                float v = s[i][j] * 0.125f;
                if (diag && (tx*4 + j > ty*4 + i)) v = -1e30f;
                s[i][j] = v;
            }

        // ---- online softmax (per row, reduce across the 16 tx lanes) ----
        #pragma unroll
        for (int i = 0; i < 4; ++i) {
            float mx = fmaxf(fmaxf(s[i][0], s[i][1]), fmaxf(s[i][2], s[i][3]));
            mx = fmaxf(mx, __shfl_xor_sync(0xffffffffu, mx, 8));
            mx = fmaxf(mx, __shfl_xor_sync(0xffffffffu, mx, 4));
            mx = fmaxf(mx, __shfl_xor_sync(0xffffffffu, mx, 2));
            mx = fmaxf(mx, __shfl_xor_sync(0xffffffffu, mx, 1));
            float mn = fmaxf(m_r[i], mx);
            float al = __expf(m_r[i] - mn);
            float sum = 0.0f;
            #pragma unroll
            for (int j = 0; j < 4; ++j) {
                float p = __expf(s[i][j] - mn);
                s[i][j] = p;
                sum += p;
            }
            sum += __shfl_xor_sync(0xffffffffu, sum, 8);
            sum += __shfl_xor_sync(0xffffffffu, sum, 4);
            sum += __shfl_xor_sync(0xffffffffu, sum, 2);
            sum += __shfl_xor_sync(0xffffffffu, sum, 1);
            l_r[i] = l_r[i] * al + sum;
            m_r[i] = mn;
            #pragma unroll
            for (int j = 0; j < 4; ++j)
                acc[i][j] *= al;
        }

        // store P transposed: Ps[n][m]
        #pragma unroll
        for (int j = 0; j < 4; ++j) {
            float4 pv = make_float4(s[0][j], s[1][j], s[2][j], s[3][j]);
            *(float4*)&Ps[(tx*4 + j)*68 + ty*4] = pv;
        }
        __syncthreads();

        // ---- O += P V ----
        #pragma unroll 8
        for (int n = 0; n < 64; ++n) {
            float4 pf = *(const float4*)&Ps[n*68 + ty*4];
            float4 vf = *(const float4*)&Vs[n*68 + tx*4];
            float pv[4] = {pf.x, pf.y, pf.z, pf.w};
            float vv[4] = {vf.x, vf.y, vf.z, vf.w};
            #pragma unroll
            for (int i = 0; i < 4; ++i)
                #pragma unroll
                for (int j = 0; j < 4; ++j)
                    acc[i][j] += pv[i] * vv[j];
        }
    }

    // epilogue: normalize and write
    #pragma unroll
    for (int i = 0; i < 4; ++i) {
        float inv = 1.0f / l_r[i];
        float4 o = make_float4(acc[i][0]*inv, acc[i][1]*inv, acc[i][2]*inv, acc[i][3]*inv);
        *(float4*)&out[base_q + (ty*4 + i)*Hq + tx*4] = o;
    }
}

// ---------------------------------------------------------------------------
extern "C" void kernel_launch(void* const* d_in, const int* in_sizes, int n_in,
                              void* d_out, int out_size)
{
    const float* x  = (const float*)d_in[0];
    const float* Wq = (const float*)d_in[1];
    const float* Wk = (const float*)d_in[2];
    const float* Wv = (const float*)d_in[3];
    float* out = (float*)d_out;

    (void)in_sizes; (void)n_in; (void)out_size;

    qkv_proj_kernel<<<BT/64, 256>>>(x, Wq, Wk, Wv);

    cudaFuncSetAttribute(attn_kernel,
                         cudaFuncAttributeMaxDynamicSharedMemorySize, ATTN_SMEM);
    attn_kernel<<<dim3(32, Bq), 256, ATTN_SMEM>>>(out);
}

// round 3
// speedup vs baseline: 1.9154x; 1.9154x over previous
#include <cuda_runtime.h>
#include <cuda_bf16.h>
#include <cstdint>

#define Bq 8
#define Tq 2048
#define Dq 1024
#define Hq 64
#define BT (Bq*Tq)
#define NQKV 192

// ---------------- device scratch (static globals: allowed) ----------------
__device__ __nv_bfloat16 g_xh[BT*Dq];
__device__ __nv_bfloat16 g_xl[BT*Dq];
__device__ __nv_bfloat16 g_wh[NQKV*Dq];   // transposed: [n][k]
__device__ __nv_bfloat16 g_wl[NQKV*Dq];
__device__ __nv_bfloat16 g_qh[BT*Hq];     // [t][h]
__device__ __nv_bfloat16 g_ql[BT*Hq];
__device__ __nv_bfloat16 g_kh[BT*Hq];     // [t][h]
__device__ __nv_bfloat16 g_kl[BT*Hq];
__device__ __nv_bfloat16 g_vhT[Hq*BT];    // transposed: [h][t]
__device__ __nv_bfloat16 g_vlT[Hq*BT];

// ---------------- mma.sync wrapper (bf16, m16n8k16, fp32 accum) -----------
__device__ __forceinline__ void mma16816(float* c, const uint32_t* a, const uint32_t* b)
{
    asm volatile(
        "mma.sync.aligned.m16n8k16.row.col.f32.bf16.bf16.f32 "
        "{%0,%1,%2,%3}, {%4,%5,%6,%7}, {%8,%9}, {%0,%1,%2,%3};"
        : "+f"(c[0]), "+f"(c[1]), "+f"(c[2]), "+f"(c[3])
        : "r"(a[0]), "r"(a[1]), "r"(a[2]), "r"(a[3]), "r"(b[0]), "r"(b[1]));
}

__device__ __forceinline__ uint32_t pack_bf2(float a, float b)
{
    __nv_bfloat162 t = __floats2bfloat162_rn(a, b);
    return *(uint32_t*)&t;
}

// ---------------------------------------------------------------------------
// Kernel 0a: split X -> (hi, lo) bf16
// ---------------------------------------------------------------------------
__global__ __launch_bounds__(256) void xsplit_kernel(const float* __restrict__ x)
{
    int i = blockIdx.x * 256 + threadIdx.x;      // float4 index
    float4 v = ((const float4*)x)[i];
    float xv[4] = {v.x, v.y, v.z, v.w};
    __nv_bfloat16 h0 = __float2bfloat16(xv[0]);
    __nv_bfloat16 h1 = __float2bfloat16(xv[1]);
    __nv_bfloat16 h2 = __float2bfloat16(xv[2]);
    __nv_bfloat16 h3 = __float2bfloat16(xv[3]);
    __nv_bfloat162 h01, h23, l01, l23;
    h01.x = h0; h01.y = h1; h23.x = h2; h23.y = h3;
    l01.x = __float2bfloat16(xv[0] - __bfloat162float(h0));
    l01.y = __float2bfloat16(xv[1] - __bfloat162float(h1));
    l23.x = __float2bfloat16(xv[2] - __bfloat162float(h2));
    l23.y = __float2bfloat16(xv[3] - __bfloat162float(h3));
    ((__nv_bfloat162*)g_xh)[i*2    ] = h01;
    ((__nv_bfloat162*)g_xh)[i*2 + 1] = h23;
    ((__nv_bfloat162*)g_xl)[i*2    ] = l01;
    ((__nv_bfloat162*)g_xl)[i*2 + 1] = l23;
}

// ---------------------------------------------------------------------------
// Kernel 0b: W -> transposed split bf16: g_wh/g_wl[n][k]
// ---------------------------------------------------------------------------
__global__ __launch_bounds__(256) void wsplit_kernel(
    const float* __restrict__ Wq, const float* __restrict__ Wk, const float* __restrict__ Wv)
{
    int n = blockIdx.x;                     // 0..191
    const float* W = (n < 64) ? Wq : (n < 128) ? Wk : Wv;
    int col = n & 63;
    for (int k = threadIdx.x; k < Dq; k += 256) {
        float v = W[k*Hq + col];
        __nv_bfloat16 hi = __float2bfloat16(v);
        g_wh[n*Dq + k] = hi;
        g_wl[n*Dq + k] = __float2bfloat16(v - __bfloat162float(hi));
    }
}

// ---------------------------------------------------------------------------
// Kernel 1: QKV GEMM via mma.sync, split-bf16 (3 products).
// C[16384,192] = X @ W^T. grid (128, 2): 128 M-tiles x 2 N-halves (96 each).
// 8 warps, each m16 x n96. Epilogue re-splits fp32 -> (hi,lo) bf16 and writes
// q,k row-major [t][h]; v transposed [h][t].
// ---------------------------------------------------------------------------
__global__ __launch_bounds__(256) void qkv_gemm_kernel()
{
    __shared__ __align__(16) __nv_bfloat16 XH[128*40];
    __shared__ __align__(16) __nv_bfloat16 XL[128*40];
    __shared__ __align__(16) __nv_bfloat16 WH[96*40];
    __shared__ __align__(16) __nv_bfloat16 WL[96*40];

    const int tid  = threadIdx.x;
    const int lane = tid & 31;
    const int warp = tid >> 5;
    const int m0   = blockIdx.x * 128;
    const int nbase= blockIdx.y * 96;

    float c[12][4];
    #pragma unroll
    for (int nt = 0; nt < 12; ++nt)
        #pragma unroll
        for (int j = 0; j < 4; ++j) c[nt][j] = 0.0f;

    const int r0 = warp*16 + (lane >> 2);
    const int qc = (lane & 3) * 2;

    for (int kc = 0; kc < Dq; kc += 32) {
        __syncthreads();
        #pragma unroll
        for (int i = tid; i < 512; i += 256) {
            int r = i >> 2, c8 = (i & 3) * 8;
            *(uint4*)&XH[r*40 + c8] = *(const uint4*)&g_xh[(size_t)(m0 + r)*Dq + kc + c8];
            *(uint4*)&XL[r*40 + c8] = *(const uint4*)&g_xl[(size_t)(m0 + r)*Dq + kc + c8];
        }
        #pragma unroll
        for (int i = tid; i < 384; i += 256) {
            int r = i >> 2, c8 = (i & 3) * 8;
            *(uint4*)&WH[r*40 + c8] = *(const uint4*)&g_wh[(size_t)(nbase + r)*Dq + kc + c8];
            *(uint4*)&WL[r*40 + c8] = *(const uint4*)&g_wl[(size_t)(nbase + r)*Dq + kc + c8];
        }
        __syncthreads();

        #pragma unroll
        for (int ks = 0; ks < 2; ++ks) {
            const int k0 = ks*16 + qc;
            uint32_t ah[4], al_[4];
            ah[0]  = *(uint32_t*)&XH[ r0     *40 + k0];
            ah[1]  = *(uint32_t*)&XH[(r0+8)  *40 + k0];
            ah[2]  = *(uint32_t*)&XH[ r0     *40 + k0 + 8];
            ah[3]  = *(uint32_t*)&XH[(r0+8)  *40 + k0 + 8];
            al_[0] = *(uint32_t*)&XL[ r0     *40 + k0];
            al_[1] = *(uint32_t*)&XL[(r0+8)  *40 + k0];
            al_[2] = *(uint32_t*)&XL[ r0     *40 + k0 + 8];
            al_[3] = *(uint32_t*)&XL[(r0+8)  *40 + k0 + 8];
            #pragma unroll
            for (int nt = 0; nt < 12; ++nt) {
                const int n = nt*8 + (lane >> 2);
                uint32_t bh[2], bl[2];
                bh[0] = *(uint32_t*)&WH[n*40 + k0];
                bh[1] = *(uint32_t*)&WH[n*40 + k0 + 8];
                bl[0] = *(uint32_t*)&WL[n*40 + k0];
                bl[1] = *(uint32_t*)&WL[n*40 + k0 + 8];
                mma16816(c[nt], ah, bh);
                mma16816(c[nt], ah, bl);
                mma16816(c[nt], al_, bh);
            }
        }
    }

    // epilogue
    #pragma unroll
    for (int nt = 0; nt < 12; ++nt) {
        const int gc = nbase + nt*8 + qc;
        #pragma unroll
        for (int hf = 0; hf < 2; ++hf) {
            const int row = m0 + r0 + hf*8;
            float v0 = c[nt][hf*2], v1 = c[nt][hf*2 + 1];
            __nv_bfloat16 b0 = __float2bfloat16(v0);
            __nv_bfloat16 b1 = __float2bfloat16(v1);
            __nv_bfloat16 e0 = __float2bfloat16(v0 - __bfloat162float(b0));
            __nv_bfloat16 e1 = __float2bfloat16(v1 - __bfloat162float(b1));
            if (gc < 64) {
                __nv_bfloat162 hh; hh.x = b0; hh.y = b1;
                __nv_bfloat162 ll; ll.x = e0; ll.y = e1;
                *(__nv_bfloat162*)&g_qh[(size_t)row*Hq + gc] = hh;
                *(__nv_bfloat162*)&g_ql[(size_t)row*Hq + gc] = ll;
            } else if (gc < 128) {
                __nv_bfloat162 hh; hh.x = b0; hh.y = b1;
                __nv_bfloat162 ll; ll.x = e0; ll.y = e1;
                *(__nv_bfloat162*)&g_kh[(size_t)row*Hq + gc - 64] = hh;
                *(__nv_bfloat162*)&g_kl[(size_t)row*Hq + gc - 64] = ll;
            } else {
                const int h = gc - 128;
                g_vhT[(size_t) h   *BT + row] = b0;
                g_vhT[(size_t)(h+1)*BT + row] = b1;
                g_vlT[(size_t) h   *BT + row] = e0;
                g_vlT[(size_t)(h+1)*BT + row] = e1;
            }
        }
    }
}

// ---------------------------------------------------------------------------
// Kernel 2: causal flash attention via mma.sync, split-bf16.
// grid (16 qtiles, 8 batches), 256 threads. BM=128 (8 warps x m16), BN=64.
// Warp-local softmax; P reused in-register as PV A-fragments.
// ---------------------------------------------------------------------------
__global__ __launch_bounds__(256) void attn_kernel(float* __restrict__ out)
{
    __shared__ __align__(16) __nv_bfloat16 KsH[64*72];
    __shared__ __align__(16) __nv_bfloat16 KsL[64*72];
    __shared__ __align__(16) __nv_bfloat16 VtH[64*72];
    __shared__ __align__(16) __nv_bfloat16 VtL[64*72];

    const int tid   = threadIdx.x;
    const int lane  = tid & 31;
    const int warp  = tid >> 5;
    const int qtile = 15 - (int)blockIdx.x;     // heavy blocks first
    const int b     = blockIdx.y;
    const int q0    = qtile * 128;
    const int qc    = (lane & 3) * 2;
    const int rql   = lane >> 2;                // row-in-warp-tile

    // cache Q fragments (hi, lo) in registers: [kstep][areg]
    uint32_t qh[4][4], ql[4][4];
    {
        const size_t rb0 = (size_t)(b*Tq + q0 + warp*16 + rql) * Hq;
        const size_t rb1 = rb0 + 8*Hq;
        #pragma unroll
        for (int ks = 0; ks < 4; ++ks) {
            int k0 = ks*16 + qc;
            qh[ks][0] = *(const uint32_t*)&g_qh[rb0 + k0];
            qh[ks][1] = *(const uint32_t*)&g_qh[rb1 + k0];
            qh[ks][2] = *(const uint32_t*)&g_qh[rb0 + k0 + 8];
            qh[ks][3] = *(const uint32_t*)&g_qh[rb1 + k0 + 8];
            ql[ks][0] = *(const uint32_t*)&g_ql[rb0 + k0];
            ql[ks][1] = *(const uint32_t*)&g_ql[rb1 + k0];
            ql[ks][2] = *(const uint32_t*)&g_ql[rb0 + k0 + 8];
            ql[ks][3] = *(const uint32_t*)&g_ql[rb1 + k0 + 8];
        }
    }

    float o[8][4];
    #pragma unroll
    for (int nt = 0; nt < 8; ++nt)
        #pragma unroll
        for (int j = 0; j < 4; ++j) o[nt][j] = 0.0f;
    float m0r = -1e30f, m1r = -1e30f, l0r = 0.0f, l1r = 0.0f;

    const int row0g = q0 + warp*16 + rql;      // global q row (and +8)
    const int ktmax = 2*qtile + 1;

    for (int kt = 0; kt <= ktmax; ++kt) {
        __syncthreads();
        // load K tile [t][h] (coalesced), V tile from transposed gmem [h][t]
        const size_t kb = (size_t)(b*Tq + kt*64) * Hq;
        const size_t vb = (size_t)(b*Tq + kt*64);
        #pragma unroll
        for (int i = tid; i < 512; i += 256) {
            int t = i >> 3, h0 = (i & 7) * 8;
            *(uint4*)&KsH[t*72 + h0] = *(const uint4*)&g_kh[kb + (size_t)t*Hq + h0];
            *(uint4*)&KsL[t*72 + h0] = *(const uint4*)&g_kl[kb + (size_t)t*Hq + h0];
        }
        #pragma unroll
        for (int i = tid; i < 512; i += 256) {
            int h = i >> 3, t0 = (i & 7) * 8;
            *(uint4*)&VtH[h*72 + t0] = *(const uint4*)&g_vhT[(size_t)h*BT + vb + t0];
            *(uint4*)&VtL[h*72 + t0] = *(const uint4*)&g_vlT[(size_t)h*BT + vb + t0];
        }
        __syncthreads();

        // ---- S = Q K^T (split: Qh*Kh + Qh*Kl + Ql*Kh) ----
        float s[8][4];
        #pragma unroll
        for (int nt = 0; nt < 8; ++nt)
            #pragma unroll
            for (int j = 0; j < 4; ++j) s[nt][j] = 0.0f;

        #pragma unroll
        for (int ks = 0; ks < 4; ++ks) {
            const int k0 = ks*16 + qc;
            #pragma unroll
            for (int nt = 0; nt < 8; ++nt) {
                const int n = nt*8 + rql;
                uint32_t bh[2], bl[2];
                bh[0] = *(uint32_t*)&KsH[n*72 + k0];
                bh[1] = *(uint32_t*)&KsH[n*72 + k0 + 8];
                bl[0] = *(uint32_t*)&KsL[n*72 + k0];
                bl[1] = *(uint32_t*)&KsL[n*72 + k0 + 8];
                mma16816(s[nt], qh[ks], bh);
                mma16816(s[nt], qh[ks], bl);
                mma16816(s[nt], ql[ks], bh);
            }
        }

        // ---- scale + causal mask ----
        const bool need_mask = (kt >= 2*qtile);
        #pragma unroll
        for (int nt = 0; nt < 8; ++nt) {
            const int colg = kt*64 + nt*8 + qc;
            #pragma unroll
            for (int j = 0; j < 4; ++j) {
                float v = s[nt][j] * 0.125f;
                if (need_mask) {
                    int cg = colg + (j & 1);
                    int rg = row0g + ((j >> 1) ? 8 : 0);
                    if (cg > rg) v = -1e30f;
                }
                s[nt][j] = v;
            }
        }

        // ---- warp-local online softmax (rows r0 and r0+8) ----
        float mx0 = -1e30f, mx1 = -1e30f;
        #pragma unroll
        for (int nt = 0; nt < 8; ++nt) {
            mx0 = fmaxf(mx0, fmaxf(s[nt][0], s[nt][1]));
            mx1 = fmaxf(mx1, fmaxf(s[nt][2], s[nt][3]));
        }
        mx0 = fmaxf(mx0, __shfl_xor_sync(0xffffffffu, mx0, 1));
        mx0 = fmaxf(mx0, __shfl_xor_sync(0xffffffffu, mx0, 2));
        mx1 = fmaxf(mx1, __shfl_xor_sync(0xffffffffu, mx1, 1));
        mx1 = fmaxf(mx1, __shfl_xor_sync(0xffffffffu, mx1, 2));
        const float mn0 = fmaxf(m0r, mx0);
        const float mn1 = fmaxf(m1r, mx1);
        const float al0 = __expf(m0r - mn0);
        const float al1 = __expf(m1r - mn1);
        m0r = mn0; m1r = mn1;

        float sum0 = 0.0f, sum1 = 0.0f;
        uint32_t pha[8], phb[8], pla[8], plb[8];
        #pragma unroll
        for (int nt = 0; nt < 8; ++nt) {
            float p0 = __expf(s[nt][0] - mn0);
            float p1 = __expf(s[nt][1] - mn0);
            float p2 = __expf(s[nt][2] - mn1);
            float p3 = __expf(s[nt][3] - mn1);
            sum0 += p0 + p1; sum1 += p2 + p3;
            __nv_bfloat16 h0 = __float2bfloat16(p0);
            __nv_bfloat16 h1 = __float2bfloat16(p1);
            __nv_bfloat16 h2 = __float2bfloat16(p2);
            __nv_bfloat16 h3 = __float2bfloat16(p3);
            __nv_bfloat162 th; th.x = h0; th.y = h1; pha[nt] = *(uint32_t*)&th;
            __nv_bfloat162 tb; tb.x = h2; tb.y = h3; phb[nt] = *(uint32_t*)&tb;
            pla[nt] = pack_bf2(p0 - __bfloat162float(h0), p1 - __bfloat162float(h1));
            plb[nt] = pack_bf2(p2 - __bfloat162float(h2), p3 - __bfloat162float(h3));
        }
        sum0 += __shfl_xor_sync(0xffffffffu, sum0, 1);
        sum0 += __shfl_xor_sync(0xffffffffu, sum0, 2);
        sum1 += __shfl_xor_sync(0xffffffffu, sum1, 1);
        sum1 += __shfl_xor_sync(0xffffffffu, sum1, 2);
        l0r = l0r * al0 + sum0;
        l1r = l1r * al1 + sum1;

        #pragma unroll
        for (int nt = 0; nt < 8; ++nt) {
            o[nt][0] *= al0; o[nt][1] *= al0;
            o[nt][2] *= al1; o[nt][3] *= al1;
        }

        // ---- O += P V (split: Ph*Vh + Ph*Vl + Pl*Vh) ----
        #pragma unroll
        for (int ks = 0; ks < 4; ++ks) {
            uint32_t pah[4] = {pha[2*ks], phb[2*ks], pha[2*ks+1], phb[2*ks+1]};
            uint32_t pal[4] = {pla[2*ks], plb[2*ks], pla[2*ks+1], plb[2*ks+1]};
            const int k0 = ks*16 + qc;
            #pragma unroll
            for (int nt = 0; nt < 8; ++nt) {
                const int n = nt*8 + rql;
                uint32_t bh[2], bl[2];
                bh[0] = *(uint32_t*)&VtH[n*72 + k0];
                bh[1] = *(uint32_t*)&VtH[n*72 + k0 + 8];
                bl[0] = *(uint32_t*)&VtL[n*72 + k0];
                bl[1] = *(uint32_t*)&VtL[n*72 + k0 + 8];
                mma16816(o[nt], pah, bh);
                mma16816(o[nt], pah, bl);
                mma16816(o[nt], pal, bh);
            }
        }
    }

    // ---- epilogue: normalize and write fp32 out [t][h] ----
    const float inv0 = 1.0f / l0r;
    const float inv1 = 1.0f / l1r;
    const size_t ob0 = (size_t)(b*Tq + row0g) * Hq;
    const size_t ob1 = ob0 + 8*Hq;
    #pragma unroll
    for (int nt = 0; nt < 8; ++nt) {
        const int col = nt*8 + qc;
        float2 v0 = make_float2(o[nt][0]*inv0, o[nt][1]*inv0);
        float2 v1 = make_float2(o[nt][2]*inv1, o[nt][3]*inv1);
        *(float2*)&out[ob0 + col] = v0;
        *(float2*)&out[ob1 + col] = v1;
    }
}

// ---------------------------------------------------------------------------
extern "C" void kernel_launch(void* const* d_in, const int* in_sizes, int n_in,
                              void* d_out, int out_size)
{
    const float* x  = (const float*)d_in[0];
    const float* Wq = (const float*)d_in[1];
    const float* Wk = (const float*)d_in[2];
    const float* Wv = (const float*)d_in[3];
    float* out = (float*)d_out;

    (void)in_sizes; (void)n_in; (void)out_size;

    xsplit_kernel<<<(BT*Dq)/(256*4), 256>>>(x);
    wsplit_kernel<<<NQKV, 256>>>(Wq, Wk, Wv);
    qkv_gemm_kernel<<<dim3(128, 2), 256>>>();
    attn_kernel<<<dim3(16, Bq), 256>>>(out);
}

// round 4
// speedup vs baseline: 2.4962x; 1.3032x over previous
#include <cuda_runtime.h>
#include <cuda_bf16.h>
#include <cstdint>

#define Bq 8
#define Tq 2048
#define Dq 1024
#define Hq 64
#define BT (Bq*Tq)
#define NQKV 192

// ---------------- device scratch (static globals: allowed) ----------------
__device__ __nv_bfloat16 g_wh[NQKV*Dq];   // transposed: [n][k]
__device__ __nv_bfloat16 g_wl[NQKV*Dq];
__device__ __nv_bfloat16 g_qh[BT*Hq];     // [t][h]
__device__ __nv_bfloat16 g_ql[BT*Hq];
__device__ __nv_bfloat16 g_kh[BT*Hq];     // [t][h]
__device__ __nv_bfloat16 g_kl[BT*Hq];
__device__ __nv_bfloat16 g_vhT[Hq*BT];    // transposed: [h][t]
__device__ __nv_bfloat16 g_vlT[Hq*BT];

// ---------------- helpers ----------------
__device__ __forceinline__ void mma16816(float* c, const uint32_t* a, const uint32_t* b)
{
    asm volatile(
        "mma.sync.aligned.m16n8k16.row.col.f32.bf16.bf16.f32 "
        "{%0,%1,%2,%3}, {%4,%5,%6,%7}, {%8,%9}, {%0,%1,%2,%3};"
        : "+f"(c[0]), "+f"(c[1]), "+f"(c[2]), "+f"(c[3])
        : "r"(a[0]), "r"(a[1]), "r"(a[2]), "r"(a[3]), "r"(b[0]), "r"(b[1]));
}

__device__ __forceinline__ uint32_t pack_bf2(float a, float b)
{
    __nv_bfloat162 t = __floats2bfloat162_rn(a, b);
    return *(uint32_t*)&t;
}

__device__ __forceinline__ uint32_t smem_u32(const void* p) {
    uint32_t a;
    asm("{ .reg .u64 t; cvta.to.shared.u64 t, %1; cvt.u32.u64 %0, t; }"
        : "=r"(a) : "l"(p));
    return a;
}

__device__ __forceinline__ void cp16(uint32_t d, const void* s) {
    asm volatile("cp.async.cg.shared.global [%0], [%1], 16;" :: "r"(d), "l"(s) : "memory");
}
#define CP_COMMIT() asm volatile("cp.async.commit_group;" ::: "memory")
#define CP_WAIT(n)  asm volatile("cp.async.wait_group %0;" :: "n"(n) : "memory")

// ---------------------------------------------------------------------------
// Kernel 0: W -> transposed split bf16: g_wh/g_wl[n][k]
// ---------------------------------------------------------------------------
__global__ __launch_bounds__(256) void wsplit_kernel(
    const float* __restrict__ Wq, const float* __restrict__ Wk, const float* __restrict__ Wv)
{
    int n = blockIdx.x;                     // 0..191
    const float* W = (n < 64) ? Wq : (n < 128) ? Wk : Wv;
    int col = n & 63;
    for (int k = threadIdx.x; k < Dq; k += 256) {
        float v = W[k*Hq + col];
        __nv_bfloat16 hi = __float2bfloat16(v);
        g_wh[n*Dq + k] = hi;
        g_wl[n*Dq + k] = __float2bfloat16(v - __bfloat162float(hi));
    }
}

// ---------------------------------------------------------------------------
// Kernel 1: fused split + QKV GEMM, double-buffered.
// C[16384,192] = X @ W^T. grid = 128 M-tiles, 256 threads, 8 warps x m16n192.
// X read fp32 from input, split to (hi,lo) bf16 while staging to smem.
// W staged via cp.async. K-chunks of 32, 2-stage pipeline.
// ---------------------------------------------------------------------------
#define QXH 0
#define QXL 10240
#define QWH 20480
#define QWL 35840
#define QST 51200
#define QSM_TOTAL (2*QST)

__global__ __launch_bounds__(256) void qkv_gemm_kernel(const float* __restrict__ x)
{
    extern __shared__ char smem[];
    const uint32_t sb = smem_u32(smem);

    const int tid  = threadIdx.x;
    const int lane = tid & 31;
    const int warp = tid >> 5;
    const int m0   = blockIdx.x * 128;

    float c[24][4];
    #pragma unroll
    for (int nt = 0; nt < 24; ++nt)
        #pragma unroll
        for (int j = 0; j < 4; ++j) c[nt][j] = 0.0f;

    const int r0 = warp*16 + (lane >> 2);
    const int qc = (lane & 3) * 2;

    float4 xr[4];

    // X prefetch: thread's 4 float4s of the 128x32 chunk
    auto loadX = [&](int kc) {
        #pragma unroll
        for (int j = 0; j < 4; ++j) {
            int i = tid + j*256;
            int r = i >> 3, c4 = i & 7;
            xr[j] = *(const float4*)&x[(size_t)(m0 + r)*Dq + kc + c4*4];
        }
    };
    // convert + store X chunk into stage
    auto stsX = [&](int stg) {
        char* s = smem + stg*QST;
        #pragma unroll
        for (int j = 0; j < 4; ++j) {
            int i = tid + j*256;
            int r = i >> 3, c4 = i & 7;
            float4 v = xr[j];
            __nv_bfloat16 h0 = __float2bfloat16(v.x);
            __nv_bfloat16 h1 = __float2bfloat16(v.y);
            __nv_bfloat16 h2 = __float2bfloat16(v.z);
            __nv_bfloat16 h3 = __float2bfloat16(v.w);
            __nv_bfloat162 ha; ha.x = h0; ha.y = h1;
            __nv_bfloat162 hb; hb.x = h2; hb.y = h3;
            __nv_bfloat162 la; la.x = __float2bfloat16(v.x - __bfloat162float(h0));
                               la.y = __float2bfloat16(v.y - __bfloat162float(h1));
            __nv_bfloat162 lb; lb.x = __float2bfloat16(v.z - __bfloat162float(h2));
                               lb.y = __float2bfloat16(v.w - __bfloat162float(h3));
            int off = (r*40 + c4*4) * 2;
            *(__nv_bfloat162*)(s + QXH + off)     = ha;
            *(__nv_bfloat162*)(s + QXH + off + 4) = hb;
            *(__nv_bfloat162*)(s + QXL + off)     = la;
            *(__nv_bfloat162*)(s + QXL + off + 4) = lb;
        }
    };
    // cp.async W chunk into stage
    auto cpW = [&](int kc, int stg) {
        uint32_t s = sb + stg*QST;
        #pragma unroll
        for (int i = tid; i < 768; i += 256) {
            int r = i >> 2, c16 = (i & 3) * 8;
            uint32_t off = (uint32_t)(r*40 + c16) * 2;
            cp16(s + QWH + off, &g_wh[(size_t)r*Dq + kc + c16]);
            cp16(s + QWL + off, &g_wl[(size_t)r*Dq + kc + c16]);
        }
    };

    // prologue: stage 0
    loadX(0);
    cpW(0, 0);
    CP_COMMIT();
    stsX(0);
    CP_WAIT(0);
    __syncthreads();

    for (int i = 0; i < 32; ++i) {
        const int cur = i & 1, nxt = cur ^ 1;
        const int kc = i * 32;
        if (i < 31) {
            cpW(kc + 32, nxt);
            CP_COMMIT();
            loadX(kc + 32);
        }

        const char* s = smem + cur*QST;
        const char* XH = s + QXH;
        const char* XL = s + QXL;
        const char* WH = s + QWH;
        const char* WL = s + QWL;

        #pragma unroll
        for (int ks = 0; ks < 2; ++ks) {
            const int k0 = ks*16 + qc;
            uint32_t ah[4], al_[4];
            ah[0]  = *(const uint32_t*)(XH + ( r0    *40 + k0    )*2);
            ah[1]  = *(const uint32_t*)(XH + ((r0+8) *40 + k0    )*2);
            ah[2]  = *(const uint32_t*)(XH + ( r0    *40 + k0 + 8)*2);
            ah[3]  = *(const uint32_t*)(XH + ((r0+8) *40 + k0 + 8)*2);
            al_[0] = *(const uint32_t*)(XL + ( r0    *40 + k0    )*2);
            al_[1] = *(const uint32_t*)(XL + ((r0+8) *40 + k0    )*2);
            al_[2] = *(const uint32_t*)(XL + ( r0    *40 + k0 + 8)*2);
            al_[3] = *(const uint32_t*)(XL + ((r0+8) *40 + k0 + 8)*2);
            #pragma unroll
            for (int nt = 0; nt < 24; ++nt) {
                const int n = nt*8 + (lane >> 2);
                uint32_t bh[2], bl[2];
                bh[0] = *(const uint32_t*)(WH + (n*40 + k0    )*2);
                bh[1] = *(const uint32_t*)(WH + (n*40 + k0 + 8)*2);
                bl[0] = *(const uint32_t*)(WL + (n*40 + k0    )*2);
                bl[1] = *(const uint32_t*)(WL + (n*40 + k0 + 8)*2);
                mma16816(c[nt], ah, bh);
                mma16816(c[nt], ah, bl);
                mma16816(c[nt], al_, bh);
            }
        }

        if (i < 31) stsX(nxt);
        CP_WAIT(0);
        __syncthreads();
    }

    // epilogue: re-split fp32 -> (hi,lo) bf16 and scatter q,k,v
    #pragma unroll
    for (int nt = 0; nt < 24; ++nt) {
        const int gc = nt*8 + qc;
        #pragma unroll
        for (int hf = 0; hf < 2; ++hf) {
            const int row = m0 + r0 + hf*8;
            float v0 = c[nt][hf*2], v1 = c[nt][hf*2 + 1];
            __nv_bfloat16 b0 = __float2bfloat16(v0);
            __nv_bfloat16 b1 = __float2bfloat16(v1);
            __nv_bfloat16 e0 = __float2bfloat16(v0 - __bfloat162float(b0));
            __nv_bfloat16 e1 = __float2bfloat16(v1 - __bfloat162float(b1));
            if (gc < 64) {
                __nv_bfloat162 hh; hh.x = b0; hh.y = b1;
                __nv_bfloat162 ll; ll.x = e0; ll.y = e1;
                *(__nv_bfloat162*)&g_qh[(size_t)row*Hq + gc] = hh;
                *(__nv_bfloat162*)&g_ql[(size_t)row*Hq + gc] = ll;
            } else if (gc < 128) {
                __nv_bfloat162 hh; hh.x = b0; hh.y = b1;
                __nv_bfloat162 ll; ll.x = e0; ll.y = e1;
                *(__nv_bfloat162*)&g_kh[(size_t)row*Hq + gc - 64] = hh;
                *(__nv_bfloat162*)&g_kl[(size_t)row*Hq + gc - 64] = ll;
            } else {
                const int h = gc - 128;
                g_vhT[(size_t) h   *BT + row] = b0;
                g_vhT[(size_t)(h+1)*BT + row] = b1;
                g_vlT[(size_t) h   *BT + row] = e0;
                g_vlT[(size_t)(h+1)*BT + row] = e1;
            }
        }
    }
}

// ---------------------------------------------------------------------------
// Kernel 2: causal flash attention via mma.sync, split-bf16, cp.async
// staggered K/V pipeline. grid (16 qtiles, 8 b), 256 thr, BM=128, BN=64.
// ---------------------------------------------------------------------------
__global__ __launch_bounds__(256) void attn_kernel(float* __restrict__ out)
{
    __shared__ __align__(16) __nv_bfloat16 KsH[64*72];
    __shared__ __align__(16) __nv_bfloat16 KsL[64*72];
    __shared__ __align__(16) __nv_bfloat16 VtH[64*72];
    __shared__ __align__(16) __nv_bfloat16 VtL[64*72];

    const int tid   = threadIdx.x;
    const int lane  = tid & 31;
    const int warp  = tid >> 5;
    const int qtile = 15 - (int)blockIdx.x;     // heavy blocks first
    const int b     = blockIdx.y;
    const int q0    = qtile * 128;
    const int qc    = (lane & 3) * 2;
    const int rql   = lane >> 2;

    const uint32_t ksh = smem_u32(KsH);
    const uint32_t ksl = smem_u32(KsL);
    const uint32_t vth = smem_u32(VtH);
    const uint32_t vtl = smem_u32(VtL);

    auto issueK = [&](int kt) {
        const size_t kb = (size_t)(b*Tq + kt*64) * Hq;
        #pragma unroll
        for (int i = tid; i < 512; i += 256) {
            int t = i >> 3, h0 = (i & 7) * 8;
            uint32_t off = (uint32_t)(t*72 + h0) * 2;
            cp16(ksh + off, &g_kh[kb + (size_t)t*Hq + h0]);
            cp16(ksl + off, &g_kl[kb + (size_t)t*Hq + h0]);
        }
    };
    auto issueV = [&](int kt) {
        const size_t vb = (size_t)(b*Tq + kt*64);
        #pragma unroll
        for (int i = tid; i < 512; i += 256) {
            int h = i >> 3, t0 = (i & 7) * 8;
            uint32_t off = (uint32_t)(h*72 + t0) * 2;
            cp16(vth + off, &g_vhT[(size_t)h*BT + vb + t0]);
            cp16(vtl + off, &g_vlT[(size_t)h*BT + vb + t0]);
        }
    };

    // Q fragments (hi, lo) in registers
    uint32_t qh[4][4], ql[4][4];
    {
        const size_t rb0 = (size_t)(b*Tq + q0 + warp*16 + rql) * Hq;
        const size_t rb1 = rb0 + 8*Hq;
        #pragma unroll
        for (int ks = 0; ks < 4; ++ks) {
            int k0 = ks*16 + qc;
            qh[ks][0] = *(const uint32_t*)&g_qh[rb0 + k0];
            qh[ks][1] = *(const uint32_t*)&g_qh[rb1 + k0];
            qh[ks][2] = *(const uint32_t*)&g_qh[rb0 + k0 + 8];
            qh[ks][3] = *(const uint32_t*)&g_qh[rb1 + k0 + 8];
            ql[ks][0] = *(const uint32_t*)&g_ql[rb0 + k0];
            ql[ks][1] = *(const uint32_t*)&g_ql[rb1 + k0];
            ql[ks][2] = *(const uint32_t*)&g_ql[rb0 + k0 + 8];
            ql[ks][3] = *(const uint32_t*)&g_ql[rb1 + k0 + 8];
        }
    }

    float o[8][4];
    #pragma unroll
    for (int nt = 0; nt < 8; ++nt)
        #pragma unroll
        for (int j = 0; j < 4; ++j) o[nt][j] = 0.0f;
    float m0r = -1e30f, m1r = -1e30f, l0r = 0.0f, l1r = 0.0f;

    const int row0g = q0 + warp*16 + rql;
    const int ktmax = 2*qtile + 1;

    // prologue: K0, V0 in flight (groups interleave K,V,K,V,...)
    issueK(0); CP_COMMIT();
    issueV(0); CP_COMMIT();

    for (int kt = 0; kt <= ktmax; ++kt) {
        CP_WAIT(1);            // K(kt) landed (V(kt) may still be in flight)
        __syncthreads();

        // ---- S = Q K^T ----
        float s[8][4];
        #pragma unroll
        for (int nt = 0; nt < 8; ++nt)
            #pragma unroll
            for (int j = 0; j < 4; ++j) s[nt][j] = 0.0f;

        #pragma unroll
        for (int ks = 0; ks < 4; ++ks) {
            const int k0 = ks*16 + qc;
            #pragma unroll
            for (int nt = 0; nt < 8; ++nt) {
                const int n = nt*8 + rql;
                uint32_t bh[2], bl[2];
                bh[0] = *(uint32_t*)&KsH[n*72 + k0];
                bh[1] = *(uint32_t*)&KsH[n*72 + k0 + 8];
                bl[0] = *(uint32_t*)&KsL[n*72 + k0];
                bl[1] = *(uint32_t*)&KsL[n*72 + k0 + 8];
                mma16816(s[nt], qh[ks], bh);
                mma16816(s[nt], qh[ks], bl);
                mma16816(s[nt], ql[ks], bh);
            }
        }

        __syncthreads();                 // all warps done with K smem
        if (kt < ktmax) { issueK(kt + 1); CP_COMMIT(); }   // overlaps softmax+PV

        // ---- scale + causal mask ----
        const bool need_mask = (kt >= 2*qtile);
        #pragma unroll
        for (int nt = 0; nt < 8; ++nt) {
            const int colg = kt*64 + nt*8 + qc;
            #pragma unroll
            for (int j = 0; j < 4; ++j) {
                float v = s[nt][j] * 0.125f;
                if (need_mask) {
                    int cg = colg + (j & 1);
                    int rg = row0g + ((j >> 1) ? 8 : 0);
                    if (cg > rg) v = -1e30f;
                }
                s[nt][j] = v;
            }
        }

        // ---- warp-local online softmax ----
        float mx0 = -1e30f, mx1 = -1e30f;
        #pragma unroll
        for (int nt = 0; nt < 8; ++nt) {
            mx0 = fmaxf(mx0, fmaxf(s[nt][0], s[nt][1]));
            mx1 = fmaxf(mx1, fmaxf(s[nt][2], s[nt][3]));
        }
        mx0 = fmaxf(mx0, __shfl_xor_sync(0xffffffffu, mx0, 1));
        mx0 = fmaxf(mx0, __shfl_xor_sync(0xffffffffu, mx0, 2));
        mx1 = fmaxf(mx1, __shfl_xor_sync(0xffffffffu, mx1, 1));
        mx1 = fmaxf(mx1, __shfl_xor_sync(0xffffffffu, mx1, 2));
        const float mn0 = fmaxf(m0r, mx0);
        const float mn1 = fmaxf(m1r, mx1);
        const float al0 = __expf(m0r - mn0);
        const float al1 = __expf(m1r - mn1);
        m0r = mn0; m1r = mn1;

        float sum0 = 0.0f, sum1 = 0.0f;
        uint32_t pha[8], phb[8], pla[8], plb[8];
        #pragma unroll
        for (int nt = 0; nt < 8; ++nt) {
            float p0 = __expf(s[nt][0] - mn0);
            float p1 = __expf(s[nt][1] - mn0);
            float p2 = __expf(s[nt][2] - mn1);
            float p3 = __expf(s[nt][3] - mn1);
            sum0 += p0 + p1; sum1 += p2 + p3;
            __nv_bfloat16 h0 = __float2bfloat16(p0);
            __nv_bfloat16 h1 = __float2bfloat16(p1);
            __nv_bfloat16 h2 = __float2bfloat16(p2);
            __nv_bfloat16 h3 = __float2bfloat16(p3);
            __nv_bfloat162 th; th.x = h0; th.y = h1; pha[nt] = *(uint32_t*)&th;
            __nv_bfloat162 tb; tb.x = h2; tb.y = h3; phb[nt] = *(uint32_t*)&tb;
            pla[nt] = pack_bf2(p0 - __bfloat162float(h0), p1 - __bfloat162float(h1));
            plb[nt] = pack_bf2(p2 - __bfloat162float(h2), p3 - __bfloat162float(h3));
        }
        sum0 += __shfl_xor_sync(0xffffffffu, sum0, 1);
        sum0 += __shfl_xor_sync(0xffffffffu, sum0, 2);
        sum1 += __shfl_xor_sync(0xffffffffu, sum1, 1);
        sum1 += __shfl_xor_sync(0xffffffffu, sum1, 2);
        l0r = l0r * al0 + sum0;
        l1r = l1r * al1 + sum1;

        #pragma unroll
        for (int nt = 0; nt < 8; ++nt) {
            o[nt][0] *= al0; o[nt][1] *= al0;
            o[nt][2] *= al1; o[nt][3] *= al1;
        }

        // ---- wait for V(kt) ----
        if (kt < ktmax) { CP_WAIT(1); } else { CP_WAIT(0); }
        __syncthreads();

        // ---- O += P V ----
        #pragma unroll
        for (int ks = 0; ks < 4; ++ks) {
            uint32_t pah[4] = {pha[2*ks], phb[2*ks], pha[2*ks+1], phb[2*ks+1]};
            uint32_t pal[4] = {pla[2*ks], plb[2*ks], pla[2*ks+1], plb[2*ks+1]};
            const int k0 = ks*16 + qc;
            #pragma unroll
            for (int nt = 0; nt < 8; ++nt) {
                const int n = nt*8 + rql;
                uint32_t bh[2], bl[2];
                bh[0] = *(uint32_t*)&VtH[n*72 + k0];
                bh[1] = *(uint32_t*)&VtH[n*72 + k0 + 8];
                bl[0] = *(uint32_t*)&VtL[n*72 + k0];
                bl[1] = *(uint32_t*)&VtL[n*72 + k0 + 8];
                mma16816(o[nt], pah, bh);
                mma16816(o[nt], pah, bl);
                mma16816(o[nt], pal, bh);
            }
        }

        __syncthreads();                 // all warps done with V smem
        if (kt < ktmax) { issueV(kt + 1); CP_COMMIT(); }   // overlaps next S
    }

    // ---- epilogue ----
    const float inv0 = 1.0f / l0r;
    const float inv1 = 1.0f / l1r;
    const size_t ob0 = (size_t)(b*Tq + row0g) * Hq;
    const size_t ob1 = ob0 + 8*Hq;
    #pragma unroll
    for (int nt = 0; nt < 8; ++nt) {
        const int col = nt*8 + qc;
        float2 v0 = make_float2(o[nt][0]*inv0, o[nt][1]*inv0);
        float2 v1 = make_float2(o[nt][2]*inv1, o[nt][3]*inv1);
        *(float2*)&out[ob0 + col] = v0;
        *(float2*)&out[ob1 + col] = v1;
    }
}

// ---------------------------------------------------------------------------
extern "C" void kernel_launch(void* const* d_in, const int* in_sizes, int n_in,
                              void* d_out, int out_size)
{
    const float* x  = (const float*)d_in[0];
    const float* Wq = (const float*)d_in[1];
    const float* Wk = (const float*)d_in[2];
    const float* Wv = (const float*)d_in[3];
    float* out = (float*)d_out;

    (void)in_sizes; (void)n_in; (void)out_size;

    wsplit_kernel<<<NQKV, 256>>>(Wq, Wk, Wv);

    cudaFuncSetAttribute(qkv_gemm_kernel,
                         cudaFuncAttributeMaxDynamicSharedMemorySize, QSM_TOTAL);
    qkv_gemm_kernel<<<128, 256, QSM_TOTAL>>>(x);

    attn_kernel<<<dim3(16, Bq), 256>>>(out);
}

// round 5
// speedup vs baseline: 2.8361x; 1.1362x over previous
#include <cuda_runtime.h>
#include <cuda_bf16.h>
#include <cstdint>

#define Bq 8
#define Tq 2048
#define Dq 1024
#define Hq 64
#define BT (Bq*Tq)
#define NQKV 192

// ---------------- device scratch (static globals: allowed) ----------------
__device__ __nv_bfloat16 g_wh[NQKV*Dq];   // transposed: [n][k]
__device__ __nv_bfloat16 g_wl[NQKV*Dq];
__device__ __nv_bfloat16 g_qh[BT*Hq];     // [t][h]
__device__ __nv_bfloat16 g_ql[BT*Hq];
__device__ __nv_bfloat16 g_kh[BT*Hq];     // [t][h]
__device__ __nv_bfloat16 g_kl[BT*Hq];
__device__ __nv_bfloat16 g_vhT[Hq*BT];    // transposed: [h][t]
__device__ __nv_bfloat16 g_vlT[Hq*BT];
// split-K attention partials: [half][b*16+qt][row][col] (unnormalized)
__device__ float  g_po[2][128][128][64];
__device__ float2 g_pml[2][128][128];     // (m, l) per row

// ---------------- helpers ----------------
__device__ __forceinline__ void mma16816(float* c, const uint32_t* a, const uint32_t* b)
{
    asm volatile(
        "mma.sync.aligned.m16n8k16.row.col.f32.bf16.bf16.f32 "
        "{%0,%1,%2,%3}, {%4,%5,%6,%7}, {%8,%9}, {%0,%1,%2,%3};"
        : "+f"(c[0]), "+f"(c[1]), "+f"(c[2]), "+f"(c[3])
        : "r"(a[0]), "r"(a[1]), "r"(a[2]), "r"(a[3]), "r"(b[0]), "r"(b[1]));
}

__device__ __forceinline__ uint32_t pack_bf2(float a, float b)
{
    __nv_bfloat162 t = __floats2bfloat162_rn(a, b);
    return *(uint32_t*)&t;
}

__device__ __forceinline__ uint32_t smem_u32(const void* p) {
    uint32_t a;
    asm("{ .reg .u64 t; cvta.to.shared.u64 t, %1; cvt.u32.u64 %0, t; }"
        : "=r"(a) : "l"(p));
    return a;
}

__device__ __forceinline__ void cp16(uint32_t d, const void* s) {
    asm volatile("cp.async.cg.shared.global [%0], [%1], 16;" :: "r"(d), "l"(s) : "memory");
}
#define CP_COMMIT() asm volatile("cp.async.commit_group;" ::: "memory")
#define CP_WAIT(n)  asm volatile("cp.async.wait_group %0;" :: "n"(n) : "memory")

// ---------------------------------------------------------------------------
// Kernel 0: W -> transposed split bf16: g_wh/g_wl[n][k]
// ---------------------------------------------------------------------------
__global__ __launch_bounds__(256) void wsplit_kernel(
    const float* __restrict__ Wq, const float* __restrict__ Wk, const float* __restrict__ Wv)
{
    int n = blockIdx.x;                     // 0..191
    const float* W = (n < 64) ? Wq : (n < 128) ? Wk : Wv;
    int col = n & 63;
    for (int k = threadIdx.x; k < Dq; k += 256) {
        float v = W[k*Hq + col];
        __nv_bfloat16 hi = __float2bfloat16(v);
        g_wh[n*Dq + k] = hi;
        g_wl[n*Dq + k] = __float2bfloat16(v - __bfloat162float(hi));
    }
}

// ---------------------------------------------------------------------------
// Kernel 1: fused split + QKV GEMM, double-buffered.
// grid = 128 M-tiles, 256 threads. Warp tiling 2m x 4n: warp = m64 x n48
// (cuts per-warp smem operand traffic ~2x vs m16 x n192).
// ---------------------------------------------------------------------------
#define QXH 0
#define QXL 10240
#define QWH 20480
#define QWL 35840
#define QST 51200
#define QSM_TOTAL (2*QST)

__global__ __launch_bounds__(256) void qkv_gemm_kernel(const float* __restrict__ x)
{
    extern __shared__ char smem[];
    const uint32_t sb = smem_u32(smem);

    const int tid  = threadIdx.x;
    const int lane = tid & 31;
    const int warp = tid >> 5;
    const int m0   = blockIdx.x * 128;
    const int wm   = warp & 1;          // m-half (64 rows)
    const int wn   = warp >> 1;         // n-quarter (48 cols)
    const int rql  = lane >> 2;
    const int qc   = (lane & 3) * 2;

    float c[4][6][4];
    #pragma unroll
    for (int mt = 0; mt < 4; ++mt)
        #pragma unroll
        for (int nt = 0; nt < 6; ++nt)
            #pragma unroll
            for (int j = 0; j < 4; ++j) c[mt][nt][j] = 0.0f;

    float4 xr[4];

    auto loadX = [&](int kc) {
        #pragma unroll
        for (int j = 0; j < 4; ++j) {
            int i = tid + j*256;
            int r = i >> 3, c4 = i & 7;
            xr[j] = *(const float4*)&x[(size_t)(m0 + r)*Dq + kc + c4*4];
        }
    };
    auto stsX = [&](int stg) {
        char* s = smem + stg*QST;
        #pragma unroll
        for (int j = 0; j < 4; ++j) {
            int i = tid + j*256;
            int r = i >> 3, c4 = i & 7;
            float4 v = xr[j];
            __nv_bfloat16 h0 = __float2bfloat16(v.x);
            __nv_bfloat16 h1 = __float2bfloat16(v.y);
            __nv_bfloat16 h2 = __float2bfloat16(v.z);
            __nv_bfloat16 h3 = __float2bfloat16(v.w);
            __nv_bfloat162 ha; ha.x = h0; ha.y = h1;
            __nv_bfloat162 hb; hb.x = h2; hb.y = h3;
            __nv_bfloat162 la; la.x = __float2bfloat16(v.x - __bfloat162float(h0));
                               la.y = __float2bfloat16(v.y - __bfloat162float(h1));
            __nv_bfloat162 lb; lb.x = __float2bfloat16(v.z - __bfloat162float(h2));
                               lb.y = __float2bfloat16(v.w - __bfloat162float(h3));
            int off = (r*40 + c4*4) * 2;
            *(__nv_bfloat162*)(s + QXH + off)     = ha;
            *(__nv_bfloat162*)(s + QXH + off + 4) = hb;
            *(__nv_bfloat162*)(s + QXL + off)     = la;
            *(__nv_bfloat162*)(s + QXL + off + 4) = lb;
        }
    };
    auto cpW = [&](int kc, int stg) {
        uint32_t s = sb + stg*QST;
        #pragma unroll
        for (int i = tid; i < 768; i += 256) {
            int r = i >> 2, c16 = (i & 3) * 8;
            uint32_t off = (uint32_t)(r*40 + c16) * 2;
            cp16(s + QWH + off, &g_wh[(size_t)r*Dq + kc + c16]);
            cp16(s + QWL + off, &g_wl[(size_t)r*Dq + kc + c16]);
        }
    };

    loadX(0);
    cpW(0, 0);
    CP_COMMIT();
    stsX(0);
    CP_WAIT(0);
    __syncthreads();

    for (int i = 0; i < 32; ++i) {
        const int cur = i & 1, nxt = cur ^ 1;
        const int kc = i * 32;
        if (i < 31) {
            cpW(kc + 32, nxt);
            CP_COMMIT();
            loadX(kc + 32);
        }

        const char* s = smem + cur*QST;
        const char* XH = s + QXH;
        const char* XL = s + QXL;
        const char* WH = s + QWH;
        const char* WL = s + QWL;

        #pragma unroll
        for (int ks = 0; ks < 2; ++ks) {
            const int k0 = ks*16 + qc;
            uint32_t ah[4][4], al_[4][4];
            #pragma unroll
            for (int mt = 0; mt < 4; ++mt) {
                const int r0 = wm*64 + mt*16 + rql;
                ah[mt][0]  = *(const uint32_t*)(XH + ( r0    *40 + k0    )*2);
                ah[mt][1]  = *(const uint32_t*)(XH + ((r0+8) *40 + k0    )*2);
                ah[mt][2]  = *(const uint32_t*)(XH + ( r0    *40 + k0 + 8)*2);
                ah[mt][3]  = *(const uint32_t*)(XH + ((r0+8) *40 + k0 + 8)*2);
                al_[mt][0] = *(const uint32_t*)(XL + ( r0    *40 + k0    )*2);
                al_[mt][1] = *(const uint32_t*)(XL + ((r0+8) *40 + k0    )*2);
                al_[mt][2] = *(const uint32_t*)(XL + ( r0    *40 + k0 + 8)*2);
                al_[mt][3] = *(const uint32_t*)(XL + ((r0+8) *40 + k0 + 8)*2);
            }
            #pragma unroll
            for (int nt = 0; nt < 6; ++nt) {
                const int n = wn*48 + nt*8 + rql;
                uint32_t bh[2], bl[2];
                bh[0] = *(const uint32_t*)(WH + (n*40 + k0    )*2);
                bh[1] = *(const uint32_t*)(WH + (n*40 + k0 + 8)*2);
                bl[0] = *(const uint32_t*)(WL + (n*40 + k0    )*2);
                bl[1] = *(const uint32_t*)(WL + (n*40 + k0 + 8)*2);
                #pragma unroll
                for (int mt = 0; mt < 4; ++mt) {
                    mma16816(c[mt][nt], ah[mt], bh);
                    mma16816(c[mt][nt], ah[mt], bl);
                    mma16816(c[mt][nt], al_[mt], bh);
                }
            }
        }

        if (i < 31) stsX(nxt);
        CP_WAIT(0);
        __syncthreads();
    }

    // epilogue: re-split fp32 -> (hi,lo) bf16 and scatter q,k,v
    #pragma unroll
    for (int mt = 0; mt < 4; ++mt) {
        #pragma unroll
        for (int nt = 0; nt < 6; ++nt) {
            const int gc = wn*48 + nt*8 + qc;
            #pragma unroll
            for (int hf = 0; hf < 2; ++hf) {
                const int row = m0 + wm*64 + mt*16 + rql + hf*8;
                float v0 = c[mt][nt][hf*2], v1 = c[mt][nt][hf*2 + 1];
                __nv_bfloat16 b0 = __float2bfloat16(v0);
                __nv_bfloat16 b1 = __float2bfloat16(v1);
                __nv_bfloat16 e0 = __float2bfloat16(v0 - __bfloat162float(b0));
                __nv_bfloat16 e1 = __float2bfloat16(v1 - __bfloat162float(b1));
                if (gc < 64) {
                    __nv_bfloat162 hh; hh.x = b0; hh.y = b1;
                    __nv_bfloat162 ll; ll.x = e0; ll.y = e1;
                    *(__nv_bfloat162*)&g_qh[(size_t)row*Hq + gc] = hh;
                    *(__nv_bfloat162*)&g_ql[(size_t)row*Hq + gc] = ll;
                } else if (gc < 128) {
                    __nv_bfloat162 hh; hh.x = b0; hh.y = b1;
                    __nv_bfloat162 ll; ll.x = e0; ll.y = e1;
                    *(__nv_bfloat162*)&g_kh[(size_t)row*Hq + gc - 64] = hh;
                    *(__nv_bfloat162*)&g_kl[(size_t)row*Hq + gc - 64] = ll;
                } else {
                    const int h = gc - 128;
                    g_vhT[(size_t) h   *BT + row] = b0;
                    g_vhT[(size_t)(h+1)*BT + row] = b1;
                    g_vlT[(size_t) h   *BT + row] = e0;
                    g_vlT[(size_t)(h+1)*BT + row] = e1;
                }
            }
        }
    }
}

// ---------------------------------------------------------------------------
// Kernel 2: split-K causal flash attention. grid (32, 8):
// blockIdx.x -> (qtile = 15 - bx/2, half = bx&1). Each CTA does half the key
// range of its qtile and writes unnormalized (O, m, l) partials.
// ---------------------------------------------------------------------------
__global__ __launch_bounds__(256) void attn_kernel()
{
    __shared__ __align__(16) __nv_bfloat16 KsH[64*72];
    __shared__ __align__(16) __nv_bfloat16 KsL[64*72];
    __shared__ __align__(16) __nv_bfloat16 VtH[64*72];
    __shared__ __align__(16) __nv_bfloat16 VtL[64*72];

    const int tid   = threadIdx.x;
    const int lane  = tid & 31;
    const int warp  = tid >> 5;
    const int qtile = 15 - ((int)blockIdx.x >> 1);   // heavy blocks first
    const int half  = blockIdx.x & 1;
    const int b     = blockIdx.y;
    const int q0    = qtile * 128;
    const int qc    = (lane & 3) * 2;
    const int rql   = lane >> 2;

    const int ktbeg = half ? (qtile + 1) : 0;
    const int ktend = half ? (2*qtile + 2) : (qtile + 1);

    const uint32_t ksh = smem_u32(KsH);
    const uint32_t ksl = smem_u32(KsL);
    const uint32_t vth = smem_u32(VtH);
    const uint32_t vtl = smem_u32(VtL);

    auto issueK = [&](int kt) {
        const size_t kb = (size_t)(b*Tq + kt*64) * Hq;
        #pragma unroll
        for (int i = tid; i < 512; i += 256) {
            int t = i >> 3, h0 = (i & 7) * 8;
            uint32_t off = (uint32_t)(t*72 + h0) * 2;
            cp16(ksh + off, &g_kh[kb + (size_t)t*Hq + h0]);
            cp16(ksl + off, &g_kl[kb + (size_t)t*Hq + h0]);
        }
    };
    auto issueV = [&](int kt) {
        const size_t vb = (size_t)(b*Tq + kt*64);
        #pragma unroll
        for (int i = tid; i < 512; i += 256) {
            int h = i >> 3, t0 = (i & 7) * 8;
            uint32_t off = (uint32_t)(h*72 + t0) * 2;
            cp16(vth + off, &g_vhT[(size_t)h*BT + vb + t0]);
            cp16(vtl + off, &g_vlT[(size_t)h*BT + vb + t0]);
        }
    };

    // Q fragments (hi, lo) in registers
    uint32_t qh[4][4], ql[4][4];
    {
        const size_t rb0 = (size_t)(b*Tq + q0 + warp*16 + rql) * Hq;
        const size_t rb1 = rb0 + 8*Hq;
        #pragma unroll
        for (int ks = 0; ks < 4; ++ks) {
            int k0 = ks*16 + qc;
            qh[ks][0] = *(const uint32_t*)&g_qh[rb0 + k0];
            qh[ks][1] = *(const uint32_t*)&g_qh[rb1 + k0];
            qh[ks][2] = *(const uint32_t*)&g_qh[rb0 + k0 + 8];
            qh[ks][3] = *(const uint32_t*)&g_qh[rb1 + k0 + 8];
            ql[ks][0] = *(const uint32_t*)&g_ql[rb0 + k0];
            ql[ks][1] = *(const uint32_t*)&g_ql[rb1 + k0];
            ql[ks][2] = *(const uint32_t*)&g_ql[rb0 + k0 + 8];
            ql[ks][3] = *(const uint32_t*)&g_ql[rb1 + k0 + 8];
        }
    }

    float o[8][4];
    #pragma unroll
    for (int nt = 0; nt < 8; ++nt)
        #pragma unroll
        for (int j = 0; j < 4; ++j) o[nt][j] = 0.0f;
    float m0r = -1e30f, m1r = -1e30f, l0r = 0.0f, l1r = 0.0f;

    const int row0g = q0 + warp*16 + rql;

    issueK(ktbeg); CP_COMMIT();
    issueV(ktbeg); CP_COMMIT();

    for (int kt = ktbeg; kt < ktend; ++kt) {
        CP_WAIT(1);
        __syncthreads();

        // ---- S = Q K^T ----
        float s[8][4];
        #pragma unroll
        for (int nt = 0; nt < 8; ++nt)
            #pragma unroll
            for (int j = 0; j < 4; ++j) s[nt][j] = 0.0f;

        #pragma unroll
        for (int ks = 0; ks < 4; ++ks) {
            const int k0 = ks*16 + qc;
            #pragma unroll
            for (int nt = 0; nt < 8; ++nt) {
                const int n = nt*8 + rql;
                uint32_t bh[2], bl[2];
                bh[0] = *(uint32_t*)&KsH[n*72 + k0];
                bh[1] = *(uint32_t*)&KsH[n*72 + k0 + 8];
                bl[0] = *(uint32_t*)&KsL[n*72 + k0];
                bl[1] = *(uint32_t*)&KsL[n*72 + k0 + 8];
                mma16816(s[nt], qh[ks], bh);
                mma16816(s[nt], qh[ks], bl);
                mma16816(s[nt], ql[ks], bh);
            }
        }

        __syncthreads();
        if (kt + 1 < ktend) { issueK(kt + 1); CP_COMMIT(); }

        // ---- scale + causal mask ----
        const bool need_mask = (kt >= 2*qtile);
        #pragma unroll
        for (int nt = 0; nt < 8; ++nt) {
            const int colg = kt*64 + nt*8 + qc;
            #pragma unroll
            for (int j = 0; j < 4; ++j) {
                float v = s[nt][j] * 0.125f;
                if (need_mask) {
                    int cg = colg + (j & 1);
                    int rg = row0g + ((j >> 1) ? 8 : 0);
                    if (cg > rg) v = -1e30f;
                }
                s[nt][j] = v;
            }
        }

        // ---- warp-local online softmax ----
        float mx0 = -1e30f, mx1 = -1e30f;
        #pragma unroll
        for (int nt = 0; nt < 8; ++nt) {
            mx0 = fmaxf(mx0, fmaxf(s[nt][0], s[nt][1]));
            mx1 = fmaxf(mx1, fmaxf(s[nt][2], s[nt][3]));
        }
        mx0 = fmaxf(mx0, __shfl_xor_sync(0xffffffffu, mx0, 1));
        mx0 = fmaxf(mx0, __shfl_xor_sync(0xffffffffu, mx0, 2));
        mx1 = fmaxf(mx1, __shfl_xor_sync(0xffffffffu, mx1, 1));
        mx1 = fmaxf(mx1, __shfl_xor_sync(0xffffffffu, mx1, 2));
        const float mn0 = fmaxf(m0r, mx0);
        const float mn1 = fmaxf(m1r, mx1);
        const float al0 = __expf(m0r - mn0);
        const float al1 = __expf(m1r - mn1);
        m0r = mn0; m1r = mn1;

        float sum0 = 0.0f, sum1 = 0.0f;
        uint32_t pha[8], phb[8], pla[8], plb[8];
        #pragma unroll
        for (int nt = 0; nt < 8; ++nt) {
            float p0 = __expf(s[nt][0] - mn0);
            float p1 = __expf(s[nt][1] - mn0);
            float p2 = __expf(s[nt][2] - mn1);
            float p3 = __expf(s[nt][3] - mn1);
            sum0 += p0 + p1; sum1 += p2 + p3;
            __nv_bfloat16 h0 = __float2bfloat16(p0);
            __nv_bfloat16 h1 = __float2bfloat16(p1);
            __nv_bfloat16 h2 = __float2bfloat16(p2);
            __nv_bfloat16 h3 = __float2bfloat16(p3);
            __nv_bfloat162 th; th.x = h0; th.y = h1; pha[nt] = *(uint32_t*)&th;
            __nv_bfloat162 tb; tb.x = h2; tb.y = h3; phb[nt] = *(uint32_t*)&tb;
            pla[nt] = pack_bf2(p0 - __bfloat162float(h0), p1 - __bfloat162float(h1));
            plb[nt] = pack_bf2(p2 - __bfloat162float(h2), p3 - __bfloat162float(h3));
        }
        sum0 += __shfl_xor_sync(0xffffffffu, sum0, 1);
        sum0 += __shfl_xor_sync(0xffffffffu, sum0, 2);
        sum1 += __shfl_xor_sync(0xffffffffu, sum1, 1);
        sum1 += __shfl_xor_sync(0xffffffffu, sum1, 2);
        l0r = l0r * al0 + sum0;
        l1r = l1r * al1 + sum1;

        #pragma unroll
        for (int nt = 0; nt < 8; ++nt) {
            o[nt][0] *= al0; o[nt][1] *= al0;
            o[nt][2] *= al1; o[nt][3] *= al1;
        }

        if (kt + 1 < ktend) { CP_WAIT(1); } else { CP_WAIT(0); }
        __syncthreads();

        // ---- O += P V ----
        #pragma unroll
        for (int ks = 0; ks < 4; ++ks) {
            uint32_t pah[4] = {pha[2*ks], phb[2*ks], pha[2*ks+1], phb[2*ks+1]};
            uint32_t pal[4] = {pla[2*ks], plb[2*ks], pla[2*ks+1], plb[2*ks+1]};
            const int k0 = ks*16 + qc;
            #pragma unroll
            for (int nt = 0; nt < 8; ++nt) {
                const int n = nt*8 + rql;
                uint32_t bh[2], bl[2];
                bh[0] = *(uint32_t*)&VtH[n*72 + k0];
                bh[1] = *(uint32_t*)&VtH[n*72 + k0 + 8];
                bl[0] = *(uint32_t*)&VtL[n*72 + k0];
                bl[1] = *(uint32_t*)&VtL[n*72 + k0 + 8];
                mma16816(o[nt], pah, bh);
                mma16816(o[nt], pah, bl);
                mma16816(o[nt], pal, bh);
            }
        }

        __syncthreads();
        if (kt + 1 < ktend) { issueV(kt + 1); CP_COMMIT(); }
    }

    // ---- epilogue: write unnormalized partials ----
    const int bq = b*16 + qtile;
    const int rl0 = warp*16 + rql;
    float* po = &g_po[half][bq][0][0];
    #pragma unroll
    for (int nt = 0; nt < 8; ++nt) {
        const int col = nt*8 + qc;
        *(float2*)&po[(size_t)rl0*64 + col]      = make_float2(o[nt][0], o[nt][1]);
        *(float2*)&po[(size_t)(rl0+8)*64 + col]  = make_float2(o[nt][2], o[nt][3]);
    }
    if ((lane & 3) == 0) {
        g_pml[half][bq][rl0]     = make_float2(m0r, l0r);
        g_pml[half][bq][rl0 + 8] = make_float2(m1r, l1r);
    }
}

// ---------------------------------------------------------------------------
// Kernel 3: merge the two key-range partials per (b, qtile) row.
// ---------------------------------------------------------------------------
__global__ __launch_bounds__(256) void merge_kernel(float* __restrict__ out)
{
    const int qt = blockIdx.x;
    const int b  = blockIdx.y;
    const int bq = b*16 + qt;
    const int tid = threadIdx.x;
    const int r  = tid >> 1;
    const int ch = (tid & 1) * 32;

    float2 A  = g_pml[0][bq][r];
    float2 Bv = g_pml[1][bq][r];
    float m  = fmaxf(A.x, Bv.x);
    float wA = __expf(A.x - m);
    float wB = __expf(Bv.x - m);
    float inv = 1.0f / (wA*A.y + wB*Bv.y);

    const float4* pa = (const float4*)&g_po[0][bq][r][ch];
    const float4* pb = (const float4*)&g_po[1][bq][r][ch];
    float4* po = (float4*)&out[((size_t)(b*Tq + qt*128 + r))*64 + ch];
    #pragma unroll
    for (int j = 0; j < 8; ++j) {
        float4 a = pa[j], c = pb[j];
        po[j] = make_float4((wA*a.x + wB*c.x)*inv, (wA*a.y + wB*c.y)*inv,
                            (wA*a.z + wB*c.z)*inv, (wA*a.w + wB*c.w)*inv);
    }
}

// ---------------------------------------------------------------------------
extern "C" void kernel_launch(void* const* d_in, const int* in_sizes, int n_in,
                              void* d_out, int out_size)
{
    const float* x  = (const float*)d_in[0];
    const float* Wq = (const float*)d_in[1];
    const float* Wk = (const float*)d_in[2];
    const float* Wv = (const float*)d_in[3];
    float* out = (float*)d_out;

    (void)in_sizes; (void)n_in; (void)out_size;

    wsplit_kernel<<<NQKV, 256>>>(Wq, Wk, Wv);

    cudaFuncSetAttribute(qkv_gemm_kernel,
                         cudaFuncAttributeMaxDynamicSharedMemorySize, QSM_TOTAL);
    qkv_gemm_kernel<<<128, 256, QSM_TOTAL>>>(x);

    attn_kernel<<<dim3(32, Bq), 256>>>();
    merge_kernel<<<dim3(16, Bq), 256>>>(out);
}

// round 6
// speedup vs baseline: 3.3053x; 1.1654x over previous
#include <cuda_runtime.h>
#include <cuda_bf16.h>
#include <cstdint>

#define Bq 8
#define Tq 2048
#define Dq 1024
#define Hq 64
#define BT (Bq*Tq)
#define NQKV 192

// ---------------- device scratch (static globals: allowed) ----------------
__device__ __nv_bfloat16 g_wh[NQKV*Dq];   // transposed: [n][k]
__device__ __nv_bfloat16 g_wl[NQKV*Dq];
__device__ __nv_bfloat16 g_qh[BT*Hq];     // [t][h]
__device__ __nv_bfloat16 g_ql[BT*Hq];
__device__ __nv_bfloat16 g_kh[BT*Hq];     // [t][h]
__device__ __nv_bfloat16 g_kl[BT*Hq];
__device__ __nv_bfloat16 g_vhT[Hq*BT];    // transposed: [h][t]
__device__ __nv_bfloat16 g_vlT[Hq*BT];
// split-K attention partials: [half][b*16+qt][row][col] (unnormalized)
__device__ float  g_po[2][128][128][64];
__device__ float2 g_pml[2][128][128];     // (m, l) per row
__device__ int    g_ctr;                  // persistent work queue
__device__ int    g_flag[128];            // per-(b,qt) completion count

// ---------------- helpers ----------------
__device__ __forceinline__ void mma16816(float* c, const uint32_t* a, const uint32_t* b)
{
    asm volatile(
        "mma.sync.aligned.m16n8k16.row.col.f32.bf16.bf16.f32 "
        "{%0,%1,%2,%3}, {%4,%5,%6,%7}, {%8,%9}, {%0,%1,%2,%3};"
        : "+f"(c[0]), "+f"(c[1]), "+f"(c[2]), "+f"(c[3])
        : "r"(a[0]), "r"(a[1]), "r"(a[2]), "r"(a[3]), "r"(b[0]), "r"(b[1]));
}

__device__ __forceinline__ uint32_t pack_bf2(float a, float b)
{
    __nv_bfloat162 t = __floats2bfloat162_rn(a, b);
    return *(uint32_t*)&t;
}

__device__ __forceinline__ uint32_t smem_u32(const void* p) {
    uint32_t a;
    asm("{ .reg .u64 t; cvta.to.shared.u64 t, %1; cvt.u32.u64 %0, t; }"
        : "=r"(a) : "l"(p));
    return a;
}

__device__ __forceinline__ void cp16(uint32_t d, const void* s) {
    asm volatile("cp.async.cg.shared.global [%0], [%1], 16;" :: "r"(d), "l"(s) : "memory");
}
#define CP_COMMIT() asm volatile("cp.async.commit_group;" ::: "memory")
#define CP_WAIT(n)  asm volatile("cp.async.wait_group %0;" :: "n"(n) : "memory")

// ---------------------------------------------------------------------------
// Kernel 0: W -> transposed split bf16 (coalesced reads, smem transpose).
// grid (16 kblocks, 3 srcs), 256 threads. Also zeroes queue/flags.
// ---------------------------------------------------------------------------
__global__ __launch_bounds__(256) void wsplit_kernel(
    const float* __restrict__ Wq, const float* __restrict__ Wk, const float* __restrict__ Wv)
{
    __shared__ float S[64][65];
    const int kb  = blockIdx.x;        // 64-k block
    const int src = blockIdx.y;        // 0=q 1=k 2=v
    const int tid = threadIdx.x;

    if (kb == 0 && src == 0) {         // reset persistent-queue state each run
        if (tid == 0) g_ctr = 0;
        if (tid < 128) g_flag[tid] = 0;
    }

    const float* W = (src == 0) ? Wq : (src == 1) ? Wk : Wv;

    #pragma unroll
    for (int i = tid; i < 1024; i += 256) {        // float4 units, coalesced
        int kk = i >> 4, h4 = (i & 15) * 4;
        float4 v = *(const float4*)&W[(size_t)(kb*64 + kk)*64 + h4];
        S[kk][h4] = v.x; S[kk][h4+1] = v.y; S[kk][h4+2] = v.z; S[kk][h4+3] = v.w;
    }
    __syncthreads();

    const int n  = tid >> 2;                       // 0..63
    const int kq = (tid & 3) * 16;                 // 16 k's per thread
    const size_t go = (size_t)(src*64 + n)*Dq + kb*64 + kq;
    #pragma unroll
    for (int j = 0; j < 16; j += 2) {
        float v0 = S[kq + j][n], v1 = S[kq + j + 1][n];
        __nv_bfloat16 h0 = __float2bfloat16(v0);
        __nv_bfloat16 h1 = __float2bfloat16(v1);
        __nv_bfloat162 hh; hh.x = h0; hh.y = h1;
        __nv_bfloat162 ll;
        ll.x = __float2bfloat16(v0 - __bfloat162float(h0));
        ll.y = __float2bfloat16(v1 - __bfloat162float(h1));
        *(__nv_bfloat162*)&g_wh[go + j] = hh;
        *(__nv_bfloat162*)&g_wl[go + j] = ll;
    }
}

// ---------------------------------------------------------------------------
// Kernel 1: fused split + QKV GEMM, double-buffered (unchanged from R5).
// ---------------------------------------------------------------------------
#define QXH 0
#define QXL 10240
#define QWH 20480
#define QWL 35840
#define QST 51200
#define QSM_TOTAL (2*QST)

__global__ __launch_bounds__(256) void qkv_gemm_kernel(const float* __restrict__ x)
{
    extern __shared__ char smem[];
    const uint32_t sb = smem_u32(smem);

    const int tid  = threadIdx.x;
    const int lane = tid & 31;
    const int warp = tid >> 5;
    const int m0   = blockIdx.x * 128;
    const int wm   = warp & 1;
    const int wn   = warp >> 1;
    const int rql  = lane >> 2;
    const int qc   = (lane & 3) * 2;

    float c[4][6][4];
    #pragma unroll
    for (int mt = 0; mt < 4; ++mt)
        #pragma unroll
        for (int nt = 0; nt < 6; ++nt)
            #pragma unroll
            for (int j = 0; j < 4; ++j) c[mt][nt][j] = 0.0f;

    float4 xr[4];

    auto loadX = [&](int kc) {
        #pragma unroll
        for (int j = 0; j < 4; ++j) {
            int i = tid + j*256;
            int r = i >> 3, c4 = i & 7;
            xr[j] = *(const float4*)&x[(size_t)(m0 + r)*Dq + kc + c4*4];
        }
    };
    auto stsX = [&](int stg) {
        char* s = smem + stg*QST;
        #pragma unroll
        for (int j = 0; j < 4; ++j) {
            int i = tid + j*256;
            int r = i >> 3, c4 = i & 7;
            float4 v = xr[j];
            __nv_bfloat16 h0 = __float2bfloat16(v.x);
            __nv_bfloat16 h1 = __float2bfloat16(v.y);
            __nv_bfloat16 h2 = __float2bfloat16(v.z);
            __nv_bfloat16 h3 = __float2bfloat16(v.w);
            __nv_bfloat162 ha; ha.x = h0; ha.y = h1;
            __nv_bfloat162 hb; hb.x = h2; hb.y = h3;
            __nv_bfloat162 la; la.x = __float2bfloat16(v.x - __bfloat162float(h0));
                               la.y = __float2bfloat16(v.y - __bfloat162float(h1));
            __nv_bfloat162 lb; lb.x = __float2bfloat16(v.z - __bfloat162float(h2));
                               lb.y = __float2bfloat16(v.w - __bfloat162float(h3));
            int off = (r*40 + c4*4) * 2;
            *(__nv_bfloat162*)(s + QXH + off)     = ha;
            *(__nv_bfloat162*)(s + QXH + off + 4) = hb;
            *(__nv_bfloat162*)(s + QXL + off)     = la;
            *(__nv_bfloat162*)(s + QXL + off + 4) = lb;
        }
    };
    auto cpW = [&](int kc, int stg) {
        uint32_t s = sb + stg*QST;
        #pragma unroll
        for (int i = tid; i < 768; i += 256) {
            int r = i >> 2, c16 = (i & 3) * 8;
            uint32_t off = (uint32_t)(r*40 + c16) * 2;
            cp16(s + QWH + off, &g_wh[(size_t)r*Dq + kc + c16]);
            cp16(s + QWL + off, &g_wl[(size_t)r*Dq + kc + c16]);
        }
    };

    loadX(0);
    cpW(0, 0);
    CP_COMMIT();
    stsX(0);
    CP_WAIT(0);
    __syncthreads();

    for (int i = 0; i < 32; ++i) {
        const int cur = i & 1, nxt = cur ^ 1;
        const int kc = i * 32;
        if (i < 31) {
            cpW(kc + 32, nxt);
            CP_COMMIT();
            loadX(kc + 32);
        }

        const char* s = smem + cur*QST;
        const char* XH = s + QXH;
        const char* XL = s + QXL;
        const char* WH = s + QWH;
        const char* WL = s + QWL;

        #pragma unroll
        for (int ks = 0; ks < 2; ++ks) {
            const int k0 = ks*16 + qc;
            uint32_t ah[4][4], al_[4][4];
            #pragma unroll
            for (int mt = 0; mt < 4; ++mt) {
                const int r0 = wm*64 + mt*16 + rql;
                ah[mt][0]  = *(const uint32_t*)(XH + ( r0    *40 + k0    )*2);
                ah[mt][1]  = *(const uint32_t*)(XH + ((r0+8) *40 + k0    )*2);
                ah[mt][2]  = *(const uint32_t*)(XH + ( r0    *40 + k0 + 8)*2);
                ah[mt][3]  = *(const uint32_t*)(XH + ((r0+8) *40 + k0 + 8)*2);
                al_[mt][0] = *(const uint32_t*)(XL + ( r0    *40 + k0    )*2);
                al_[mt][1] = *(const uint32_t*)(XL + ((r0+8) *40 + k0    )*2);
                al_[mt][2] = *(const uint32_t*)(XL + ( r0    *40 + k0 + 8)*2);
                al_[mt][3] = *(const uint32_t*)(XL + ((r0+8) *40 + k0 + 8)*2);
            }
            #pragma unroll
            for (int nt = 0; nt < 6; ++nt) {
                const int n = wn*48 + nt*8 + rql;
                uint32_t bh[2], bl[2];
                bh[0] = *(const uint32_t*)(WH + (n*40 + k0    )*2);
                bh[1] = *(const uint32_t*)(WH + (n*40 + k0 + 8)*2);
                bl[0] = *(const uint32_t*)(WL + (n*40 + k0    )*2);
                bl[1] = *(const uint32_t*)(WL + (n*40 + k0 + 8)*2);
                #pragma unroll
                for (int mt = 0; mt < 4; ++mt) {
                    mma16816(c[mt][nt], ah[mt], bh);
                    mma16816(c[mt][nt], ah[mt], bl);
                    mma16816(c[mt][nt], al_[mt], bh);
                }
            }
        }

        if (i < 31) stsX(nxt);
        CP_WAIT(0);
        __syncthreads();
    }

    // epilogue: re-split fp32 -> (hi,lo) bf16 and scatter q,k,v
    #pragma unroll
    for (int mt = 0; mt < 4; ++mt) {
        #pragma unroll
        for (int nt = 0; nt < 6; ++nt) {
            const int gc = wn*48 + nt*8 + qc;
            #pragma unroll
            for (int hf = 0; hf < 2; ++hf) {
                const int row = m0 + wm*64 + mt*16 + rql + hf*8;
                float v0 = c[mt][nt][hf*2], v1 = c[mt][nt][hf*2 + 1];
                __nv_bfloat16 b0 = __float2bfloat16(v0);
                __nv_bfloat16 b1 = __float2bfloat16(v1);
                __nv_bfloat16 e0 = __float2bfloat16(v0 - __bfloat162float(b0));
                __nv_bfloat16 e1 = __float2bfloat16(v1 - __bfloat162float(b1));
                if (gc < 64) {
                    __nv_bfloat162 hh; hh.x = b0; hh.y = b1;
                    __nv_bfloat162 ll; ll.x = e0; ll.y = e1;
                    *(__nv_bfloat162*)&g_qh[(size_t)row*Hq + gc] = hh;
                    *(__nv_bfloat162*)&g_ql[(size_t)row*Hq + gc] = ll;
                } else if (gc < 128) {
                    __nv_bfloat162 hh; hh.x = b0; hh.y = b1;
                    __nv_bfloat162 ll; ll.x = e0; ll.y = e1;
                    *(__nv_bfloat162*)&g_kh[(size_t)row*Hq + gc - 64] = hh;
                    *(__nv_bfloat162*)&g_kl[(size_t)row*Hq + gc - 64] = ll;
                } else {
                    const int h = gc - 128;
                    g_vhT[(size_t) h   *BT + row] = b0;
                    g_vhT[(size_t)(h+1)*BT + row] = b1;
                    g_vlT[(size_t) h   *BT + row] = e0;
                    g_vlT[(size_t)(h+1)*BT + row] = e1;
                }
            }
        }
    }
}

// ---------------------------------------------------------------------------
// Kernel 2: persistent split-K causal flash attention + fused merge.
// grid = 148 (one CTA/SM). Items popped heavy-first from a global queue:
// item i: qtile = 15 - (i>>4), b = (i&15)>>1, half = i&1.
// Last CTA to finish a (b,qtile) merges the two partials and writes out.
// ---------------------------------------------------------------------------
#define NITEMS 256

__global__ __launch_bounds__(256) void attn_kernel(float* __restrict__ out)
{
    __shared__ __align__(16) __nv_bfloat16 KsH[64*72];
    __shared__ __align__(16) __nv_bfloat16 KsL[64*72];
    __shared__ __align__(16) __nv_bfloat16 VtH[64*72];
    __shared__ __align__(16) __nv_bfloat16 VtL[64*72];
    __shared__ int s_item, s_done;

    const int tid   = threadIdx.x;
    const int lane  = tid & 31;
    const int warp  = tid >> 5;
    const int qc    = (lane & 3) * 2;
    const int rql   = lane >> 2;

    const uint32_t ksh = smem_u32(KsH);
    const uint32_t ksl = smem_u32(KsL);
    const uint32_t vth = smem_u32(VtH);
    const uint32_t vtl = smem_u32(VtL);

    while (true) {
        __syncthreads();                  // protect s_item / smem reuse
        if (tid == 0) s_item = atomicAdd(&g_ctr, 1);
        __syncthreads();
        const int item = s_item;
        if (item >= NITEMS) break;

        const int qtile = 15 - (item >> 4);
        const int inner = item & 15;
        const int b     = inner >> 1;
        const int half  = inner & 1;
        const int q0    = qtile * 128;
        const int bq    = b*16 + qtile;

        const int ktbeg = half ? (qtile + 1) : 0;
        const int ktend = half ? (2*qtile + 2) : (qtile + 1);

        auto issueK = [&](int kt) {
            const size_t kb = (size_t)(b*Tq + kt*64) * Hq;
            #pragma unroll
            for (int i = tid; i < 512; i += 256) {
                int t = i >> 3, h0 = (i & 7) * 8;
                uint32_t off = (uint32_t)(t*72 + h0) * 2;
                cp16(ksh + off, &g_kh[kb + (size_t)t*Hq + h0]);
                cp16(ksl + off, &g_kl[kb + (size_t)t*Hq + h0]);
            }
        };
        auto issueV = [&](int kt) {
            const size_t vb = (size_t)(b*Tq + kt*64);
            #pragma unroll
            for (int i = tid; i < 512; i += 256) {
                int h = i >> 3, t0 = (i & 7) * 8;
                uint32_t off = (uint32_t)(h*72 + t0) * 2;
                cp16(vth + off, &g_vhT[(size_t)h*BT + vb + t0]);
                cp16(vtl + off, &g_vlT[(size_t)h*BT + vb + t0]);
            }
        };

        // Q fragments (hi, lo) in registers
        uint32_t qh[4][4], ql[4][4];
        {
            const size_t rb0 = (size_t)(b*Tq + q0 + warp*16 + rql) * Hq;
            const size_t rb1 = rb0 + 8*Hq;
            #pragma unroll
            for (int ks = 0; ks < 4; ++ks) {
                int k0 = ks*16 + qc;
                qh[ks][0] = *(const uint32_t*)&g_qh[rb0 + k0];
                qh[ks][1] = *(const uint32_t*)&g_qh[rb1 + k0];
                qh[ks][2] = *(const uint32_t*)&g_qh[rb0 + k0 + 8];
                qh[ks][3] = *(const uint32_t*)&g_qh[rb1 + k0 + 8];
                ql[ks][0] = *(const uint32_t*)&g_ql[rb0 + k0];
                ql[ks][1] = *(const uint32_t*)&g_ql[rb1 + k0];
                ql[ks][2] = *(const uint32_t*)&g_ql[rb0 + k0 + 8];
                ql[ks][3] = *(const uint32_t*)&g_ql[rb1 + k0 + 8];
            }
        }

        float o[8][4];
        #pragma unroll
        for (int nt = 0; nt < 8; ++nt)
            #pragma unroll
            for (int j = 0; j < 4; ++j) o[nt][j] = 0.0f;
        float m0r = -1e30f, m1r = -1e30f, l0r = 0.0f, l1r = 0.0f;

        const int row0g = q0 + warp*16 + rql;

        issueK(ktbeg); CP_COMMIT();
        issueV(ktbeg); CP_COMMIT();

        for (int kt = ktbeg; kt < ktend; ++kt) {
            CP_WAIT(1);
            __syncthreads();

            // ---- S = Q K^T ----
            float s[8][4];
            #pragma unroll
            for (int nt = 0; nt < 8; ++nt)
                #pragma unroll
                for (int j = 0; j < 4; ++j) s[nt][j] = 0.0f;

            #pragma unroll
            for (int ks = 0; ks < 4; ++ks) {
                const int k0 = ks*16 + qc;
                #pragma unroll
                for (int nt = 0; nt < 8; ++nt) {
                    const int n = nt*8 + rql;
                    uint32_t bh[2], bl[2];
                    bh[0] = *(uint32_t*)&KsH[n*72 + k0];
                    bh[1] = *(uint32_t*)&KsH[n*72 + k0 + 8];
                    bl[0] = *(uint32_t*)&KsL[n*72 + k0];
                    bl[1] = *(uint32_t*)&KsL[n*72 + k0 + 8];
                    mma16816(s[nt], qh[ks], bh);
                    mma16816(s[nt], qh[ks], bl);
                    mma16816(s[nt], ql[ks], bh);
                }
            }

            __syncthreads();
            if (kt + 1 < ktend) { issueK(kt + 1); CP_COMMIT(); }

            // ---- scale + causal mask ----
            const bool need_mask = (kt >= 2*qtile);
            #pragma unroll
            for (int nt = 0; nt < 8; ++nt) {
                const int colg = kt*64 + nt*8 + qc;
                #pragma unroll
                for (int j = 0; j < 4; ++j) {
                    float v = s[nt][j] * 0.125f;
                    if (need_mask) {
                        int cg = colg + (j & 1);
                        int rg = row0g + ((j >> 1) ? 8 : 0);
                        if (cg > rg) v = -1e30f;
                    }
                    s[nt][j] = v;
                }
            }

            // ---- warp-local online softmax ----
            float mx0 = -1e30f, mx1 = -1e30f;
            #pragma unroll
            for (int nt = 0; nt < 8; ++nt) {
                mx0 = fmaxf(mx0, fmaxf(s[nt][0], s[nt][1]));
                mx1 = fmaxf(mx1, fmaxf(s[nt][2], s[nt][3]));
            }
            mx0 = fmaxf(mx0, __shfl_xor_sync(0xffffffffu, mx0, 1));
            mx0 = fmaxf(mx0, __shfl_xor_sync(0xffffffffu, mx0, 2));
            mx1 = fmaxf(mx1, __shfl_xor_sync(0xffffffffu, mx1, 1));
            mx1 = fmaxf(mx1, __shfl_xor_sync(0xffffffffu, mx1, 2));
            const float mn0 = fmaxf(m0r, mx0);
            const float mn1 = fmaxf(m1r, mx1);
            const float al0 = __expf(m0r - mn0);
            const float al1 = __expf(m1r - mn1);
            m0r = mn0; m1r = mn1;

            float sum0 = 0.0f, sum1 = 0.0f;
            uint32_t pha[8], phb[8], pla[8], plb[8];
            #pragma unroll
            for (int nt = 0; nt < 8; ++nt) {
                float p0 = __expf(s[nt][0] - mn0);
                float p1 = __expf(s[nt][1] - mn0);
                float p2 = __expf(s[nt][2] - mn1);
                float p3 = __expf(s[nt][3] - mn1);
                sum0 += p0 + p1; sum1 += p2 + p3;
                __nv_bfloat16 h0 = __float2bfloat16(p0);
                __nv_bfloat16 h1 = __float2bfloat16(p1);
                __nv_bfloat16 h2 = __float2bfloat16(p2);
                __nv_bfloat16 h3 = __float2bfloat16(p3);
                __nv_bfloat162 th; th.x = h0; th.y = h1; pha[nt] = *(uint32_t*)&th;
                __nv_bfloat162 tb; tb.x = h2; tb.y = h3; phb[nt] = *(uint32_t*)&tb;
                pla[nt] = pack_bf2(p0 - __bfloat162float(h0), p1 - __bfloat162float(h1));
                plb[nt] = pack_bf2(p2 - __bfloat162float(h2), p3 - __bfloat162float(h3));
            }
            sum0 += __shfl_xor_sync(0xffffffffu, sum0, 1);
            sum0 += __shfl_xor_sync(0xffffffffu, sum0, 2);
            sum1 += __shfl_xor_sync(0xffffffffu, sum1, 1);
            sum1 += __shfl_xor_sync(0xffffffffu, sum1, 2);
            l0r = l0r * al0 + sum0;
            l1r = l1r * al1 + sum1;

            #pragma unroll
            for (int nt = 0; nt < 8; ++nt) {
                o[nt][0] *= al0; o[nt][1] *= al0;
                o[nt][2] *= al1; o[nt][3] *= al1;
            }

            if (kt + 1 < ktend) { CP_WAIT(1); } else { CP_WAIT(0); }
            __syncthreads();

            // ---- O += P V ----
            #pragma unroll
            for (int ks = 0; ks < 4; ++ks) {
                uint32_t pah[4] = {pha[2*ks], phb[2*ks], pha[2*ks+1], phb[2*ks+1]};
                uint32_t pal[4] = {pla[2*ks], plb[2*ks], pla[2*ks+1], plb[2*ks+1]};
                const int k0 = ks*16 + qc;
                #pragma unroll
                for (int nt = 0; nt < 8; ++nt) {
                    const int n = nt*8 + rql;
                    uint32_t bh[2], bl[2];
                    bh[0] = *(uint32_t*)&VtH[n*72 + k0];
                    bh[1] = *(uint32_t*)&VtH[n*72 + k0 + 8];
                    bl[0] = *(uint32_t*)&VtL[n*72 + k0];
                    bl[1] = *(uint32_t*)&VtL[n*72 + k0 + 8];
                    mma16816(o[nt], pah, bh);
                    mma16816(o[nt], pah, bl);
                    mma16816(o[nt], pal, bh);
                }
            }

            __syncthreads();
            if (kt + 1 < ktend) { issueV(kt + 1); CP_COMMIT(); }
        }

        // ---- write unnormalized partials ----
        const int rl0 = warp*16 + rql;
        float* po = &g_po[half][bq][0][0];
        #pragma unroll
        for (int nt = 0; nt < 8; ++nt) {
            const int col = nt*8 + qc;
            *(float2*)&po[(size_t)rl0*64 + col]      = make_float2(o[nt][0], o[nt][1]);
            *(float2*)&po[(size_t)(rl0+8)*64 + col]  = make_float2(o[nt][2], o[nt][3]);
        }
        if ((lane & 3) == 0) {
            g_pml[half][bq][rl0]     = make_float2(m0r, l0r);
            g_pml[half][bq][rl0 + 8] = make_float2(m1r, l1r);
        }

        // ---- last finisher merges ----
        __threadfence();
        __syncthreads();
        if (tid == 0) s_done = atomicAdd(&g_flag[bq], 1);
        __syncthreads();
        if (s_done == 1) {
            __threadfence();             // acquire: other CTA's partials
            const int r  = tid >> 1;
            const int ch = (tid & 1) * 32;
            float2 A  = g_pml[0][bq][r];
            float2 Bv = g_pml[1][bq][r];
            float m  = fmaxf(A.x, Bv.x);
            float wA = __expf(A.x - m);
            float wB = __expf(Bv.x - m);
            float inv = 1.0f / (wA*A.y + wB*Bv.y);
            const float4* pa = (const float4*)&g_po[0][bq][r][ch];
            const float4* pb = (const float4*)&g_po[1][bq][r][ch];
            float4* pw = (float4*)&out[((size_t)(b*Tq + q0 + r))*64 + ch];
            #pragma unroll
            for (int j = 0; j < 8; ++j) {
                float4 a = pa[j], c = pb[j];
                pw[j] = make_float4((wA*a.x + wB*c.x)*inv, (wA*a.y + wB*c.y)*inv,
                                    (wA*a.z + wB*c.z)*inv, (wA*a.w + wB*c.w)*inv);
            }
        }
    }
}

// ---------------------------------------------------------------------------
extern "C" void kernel_launch(void* const* d_in, const int* in_sizes, int n_in,
                              void* d_out, int out_size)
{
    const float* x  = (const float*)d_in[0];
    const float* Wq = (const float*)d_in[1];
    const float* Wk = (const float*)d_in[2];
    const float* Wv = (const float*)d_in[3];
    float* out = (float*)d_out;

    (void)in_sizes; (void)n_in; (void)out_size;

    wsplit_kernel<<<dim3(16, 3), 256>>>(Wq, Wk, Wv);

    cudaFuncSetAttribute(qkv_gemm_kernel,
                         cudaFuncAttributeMaxDynamicSharedMemorySize, QSM_TOTAL);
    qkv_gemm_kernel<<<128, 256, QSM_TOTAL>>>(x);

    attn_kernel<<<148, 256>>>(out);
}

// round 7
// speedup vs baseline: 3.5143x; 1.0632x over previous
#include <cuda_runtime.h>
#include <cuda_bf16.h>
#include <cstdint>

#define Bq 8
#define Tq 2048
#define Dq 1024
#define Hq 64
#define BT (Bq*Tq)
#define NQKV 192

// ---------------- device scratch (static globals: allowed) ----------------
__device__ __nv_bfloat16 g_wh[NQKV*Dq];   // transposed: [n][k]
__device__ __nv_bfloat16 g_wl[NQKV*Dq];
__device__ __nv_bfloat16 g_qh[BT*Hq];     // [t][h]
__device__ __nv_bfloat16 g_ql[BT*Hq];
__device__ __nv_bfloat16 g_kh[BT*Hq];     // [t][h]
__device__ __nv_bfloat16 g_kl[BT*Hq];
__device__ __nv_bfloat16 g_vhT[Hq*BT];    // transposed: [h][t]
__device__ __nv_bfloat16 g_vlT[Hq*BT];
__device__ float  g_po[2][128][128][64];
__device__ float2 g_pml[2][128][128];
__device__ int    g_ctr;
__device__ int    g_flag[128];

// ---------------- helpers ----------------
__device__ __forceinline__ void mma16816(float* c, const uint32_t* a, const uint32_t* b)
{
    asm volatile(
        "mma.sync.aligned.m16n8k16.row.col.f32.bf16.bf16.f32 "
        "{%0,%1,%2,%3}, {%4,%5,%6,%7}, {%8,%9}, {%0,%1,%2,%3};"
        : "+f"(c[0]), "+f"(c[1]), "+f"(c[2]), "+f"(c[3])
        : "r"(a[0]), "r"(a[1]), "r"(a[2]), "r"(a[3]), "r"(b[0]), "r"(b[1]));
}

__device__ __forceinline__ void ldsm4(uint32_t* r, uint32_t addr)
{
    asm volatile("ldmatrix.sync.aligned.m8n8.x4.shared.b16 {%0,%1,%2,%3}, [%4];"
        : "=r"(r[0]), "=r"(r[1]), "=r"(r[2]), "=r"(r[3]) : "r"(addr));
}

__device__ __forceinline__ float ex2(float x)
{
    float y;
    asm("ex2.approx.f32 %0, %1;" : "=f"(y) : "f"(x));
    return y;
}

__device__ __forceinline__ uint32_t pack_bf2(float a, float b)
{
    __nv_bfloat162 t = __floats2bfloat162_rn(a, b);
    return *(uint32_t*)&t;
}

__device__ __forceinline__ uint32_t smem_u32(const void* p) {
    uint32_t a;
    asm("{ .reg .u64 t; cvta.to.shared.u64 t, %1; cvt.u32.u64 %0, t; }"
        : "=r"(a) : "l"(p));
    return a;
}

__device__ __forceinline__ void cp16(uint32_t d, const void* s) {
    asm volatile("cp.async.cg.shared.global [%0], [%1], 16;" :: "r"(d), "l"(s) : "memory");
}
#define CP_COMMIT() asm volatile("cp.async.commit_group;" ::: "memory")
#define CP_WAIT(n)  asm volatile("cp.async.wait_group %0;" :: "n"(n) : "memory")

// ---------------------------------------------------------------------------
// Kernel 0: W -> transposed split bf16 (coalesced + smem transpose).
// Also resets the persistent queue state each replay.
// ---------------------------------------------------------------------------
__global__ __launch_bounds__(256) void wsplit_kernel(
    const float* __restrict__ Wq, const float* __restrict__ Wk, const float* __restrict__ Wv)
{
    __shared__ float S[64][65];
    const int kb  = blockIdx.x;
    const int src = blockIdx.y;
    const int tid = threadIdx.x;

    if (kb == 0 && src == 0) {
        if (tid == 0) g_ctr = 0;
        if (tid < 128) g_flag[tid] = 0;
    }

    const float* W = (src == 0) ? Wq : (src == 1) ? Wk : Wv;

    #pragma unroll
    for (int i = tid; i < 1024; i += 256) {
        int kk = i >> 4, h4 = (i & 15) * 4;
        float4 v = *(const float4*)&W[(size_t)(kb*64 + kk)*64 + h4];
        S[kk][h4] = v.x; S[kk][h4+1] = v.y; S[kk][h4+2] = v.z; S[kk][h4+3] = v.w;
    }
    __syncthreads();

    const int n  = tid >> 2;
    const int kq = (tid & 3) * 16;
    const size_t go = (size_t)(src*64 + n)*Dq + kb*64 + kq;
    #pragma unroll
    for (int j = 0; j < 16; j += 2) {
        float v0 = S[kq + j][n], v1 = S[kq + j + 1][n];
        __nv_bfloat16 h0 = __float2bfloat16(v0);
        __nv_bfloat16 h1 = __float2bfloat16(v1);
        __nv_bfloat162 hh; hh.x = h0; hh.y = h1;
        __nv_bfloat162 ll;
        ll.x = __float2bfloat16(v0 - __bfloat162float(h0));
        ll.y = __float2bfloat16(v1 - __bfloat162float(h1));
        *(__nv_bfloat162*)&g_wh[go + j] = hh;
        *(__nv_bfloat162*)&g_wl[go + j] = ll;
    }
}

// ---------------------------------------------------------------------------
// Kernel 1: fused split + QKV GEMM, double-buffered, ldmatrix fragments.
// ---------------------------------------------------------------------------
#define QXH 0
#define QXL 10240
#define QWH 20480
#define QWL 35840
#define QST 51200
#define QSM_TOTAL (2*QST)

__global__ __launch_bounds__(256) void qkv_gemm_kernel(const float* __restrict__ x)
{
    extern __shared__ char smem[];
    const uint32_t sb = smem_u32(smem);

    const int tid  = threadIdx.x;
    const int lane = tid & 31;
    const int warp = tid >> 5;
    const int m0   = blockIdx.x * 128;
    const int wm   = warp & 1;
    const int wn   = warp >> 1;
    const int rql  = lane >> 2;
    const int qc   = (lane & 3) * 2;

    // ldmatrix per-lane offsets (row strides of 40 elems = 80B)
    const int arow = (lane & 7) + (((lane >> 3) & 1) << 3);   // A: m-row in 16
    const int acol = (lane >> 4) << 3;                        // A: k-col 0/8
    const uint32_t axoff = (uint32_t)(arow*40 + acol) * 2;
    const int brow = (lane & 7) + ((lane >> 4) << 3);         // B: n-row in 16
    const int bcol = ((lane >> 3) & 1) << 3;                  // B: k-col 0/8
    const uint32_t bxoff = (uint32_t)(brow*40 + bcol) * 2;

    float c[4][6][4];
    #pragma unroll
    for (int mt = 0; mt < 4; ++mt)
        #pragma unroll
        for (int nt = 0; nt < 6; ++nt)
            #pragma unroll
            for (int j = 0; j < 4; ++j) c[mt][nt][j] = 0.0f;

    float4 xr[4];

    auto loadX = [&](int kc) {
        #pragma unroll
        for (int j = 0; j < 4; ++j) {
            int i = tid + j*256;
            int r = i >> 3, c4 = i & 7;
            xr[j] = *(const float4*)&x[(size_t)(m0 + r)*Dq + kc + c4*4];
        }
    };
    auto stsX = [&](int stg) {
        char* s = smem + stg*QST;
        #pragma unroll
        for (int j = 0; j < 4; ++j) {
            int i = tid + j*256;
            int r = i >> 3, c4 = i & 7;
            float4 v = xr[j];
            __nv_bfloat16 h0 = __float2bfloat16(v.x);
            __nv_bfloat16 h1 = __float2bfloat16(v.y);
            __nv_bfloat16 h2 = __float2bfloat16(v.z);
            __nv_bfloat16 h3 = __float2bfloat16(v.w);
            __nv_bfloat162 ha; ha.x = h0; ha.y = h1;
            __nv_bfloat162 hb; hb.x = h2; hb.y = h3;
            __nv_bfloat162 la; la.x = __float2bfloat16(v.x - __bfloat162float(h0));
                               la.y = __float2bfloat16(v.y - __bfloat162float(h1));
            __nv_bfloat162 lb; lb.x = __float2bfloat16(v.z - __bfloat162float(h2));
                               lb.y = __float2bfloat16(v.w - __bfloat162float(h3));
            int off = (r*40 + c4*4) * 2;
            *(__nv_bfloat162*)(s + QXH + off)     = ha;
            *(__nv_bfloat162*)(s + QXH + off + 4) = hb;
            *(__nv_bfloat162*)(s + QXL + off)     = la;
            *(__nv_bfloat162*)(s + QXL + off + 4) = lb;
        }
    };
    auto cpW = [&](int kc, int stg) {
        uint32_t s = sb + stg*QST;
        #pragma unroll
        for (int i = tid; i < 768; i += 256) {
            int r = i >> 2, c16 = (i & 3) * 8;
            uint32_t off = (uint32_t)(r*40 + c16) * 2;
            cp16(s + QWH + off, &g_wh[(size_t)r*Dq + kc + c16]);
            cp16(s + QWL + off, &g_wl[(size_t)r*Dq + kc + c16]);
        }
    };

    loadX(0);
    cpW(0, 0);
    CP_COMMIT();
    stsX(0);
    CP_WAIT(0);
    __syncthreads();

    for (int i = 0; i < 32; ++i) {
        const int cur = i & 1, nxt = cur ^ 1;
        const int kc = i * 32;
        if (i < 31) {
            cpW(kc + 32, nxt);
            CP_COMMIT();
            loadX(kc + 32);
        }

        const uint32_t sc = sb + cur*QST;

        #pragma unroll
        for (int ks = 0; ks < 2; ++ks) {
            const int k0 = ks*16;
            uint32_t ah[4][4], al_[4][4];
            #pragma unroll
            for (int mt = 0; mt < 4; ++mt) {
                uint32_t a = sc + QXH + (uint32_t)((wm*64 + mt*16)*40 + k0)*2 + axoff;
                ldsm4(ah[mt], a);
                ldsm4(al_[mt], a + (QXL - QXH));
            }
            #pragma unroll
            for (int ntp = 0; ntp < 3; ++ntp) {
                uint32_t bh[4], bl[4];
                uint32_t bA = sc + QWH + (uint32_t)((wn*48 + ntp*16)*40 + k0)*2 + bxoff;
                ldsm4(bh, bA);
                ldsm4(bl, bA + (QWL - QWH));
                #pragma unroll
                for (int mt = 0; mt < 4; ++mt) {
                    mma16816(c[mt][2*ntp],   ah[mt], &bh[0]);
                    mma16816(c[mt][2*ntp],   ah[mt], &bl[0]);
                    mma16816(c[mt][2*ntp],   al_[mt], &bh[0]);
                    mma16816(c[mt][2*ntp+1], ah[mt], &bh[2]);
                    mma16816(c[mt][2*ntp+1], ah[mt], &bl[2]);
                    mma16816(c[mt][2*ntp+1], al_[mt], &bh[2]);
                }
            }
        }

        if (i < 31) stsX(nxt);
        CP_WAIT(0);
        __syncthreads();
    }

    // epilogue: re-split fp32 -> (hi,lo) bf16 and scatter q,k,v
    #pragma unroll
    for (int mt = 0; mt < 4; ++mt) {
        #pragma unroll
        for (int nt = 0; nt < 6; ++nt) {
            const int gc = wn*48 + nt*8 + qc;
            #pragma unroll
            for (int hf = 0; hf < 2; ++hf) {
                const int row = m0 + wm*64 + mt*16 + rql + hf*8;
                float v0 = c[mt][nt][hf*2], v1 = c[mt][nt][hf*2 + 1];
                __nv_bfloat16 b0 = __float2bfloat16(v0);
                __nv_bfloat16 b1 = __float2bfloat16(v1);
                __nv_bfloat16 e0 = __float2bfloat16(v0 - __bfloat162float(b0));
                __nv_bfloat16 e1 = __float2bfloat16(v1 - __bfloat162float(b1));
                if (gc < 64) {
                    __nv_bfloat162 hh; hh.x = b0; hh.y = b1;
                    __nv_bfloat162 ll; ll.x = e0; ll.y = e1;
                    *(__nv_bfloat162*)&g_qh[(size_t)row*Hq + gc] = hh;
                    *(__nv_bfloat162*)&g_ql[(size_t)row*Hq + gc] = ll;
                } else if (gc < 128) {
                    __nv_bfloat162 hh; hh.x = b0; hh.y = b1;
                    __nv_bfloat162 ll; ll.x = e0; ll.y = e1;
                    *(__nv_bfloat162*)&g_kh[(size_t)row*Hq + gc - 64] = hh;
                    *(__nv_bfloat162*)&g_kl[(size_t)row*Hq + gc - 64] = ll;
                } else {
                    const int h = gc - 128;
                    g_vhT[(size_t) h   *BT + row] = b0;
                    g_vhT[(size_t)(h+1)*BT + row] = b1;
                    g_vlT[(size_t) h   *BT + row] = e0;
                    g_vlT[(size_t)(h+1)*BT + row] = e1;
                }
            }
        }
    }
}

// ---------------------------------------------------------------------------
// Kernel 2: persistent split-K flash attention + fused merge.
// Double-buffered K/V (one commit group per stage), ldmatrix B-fragments,
// exp2-domain softmax. grid = 148.
// ---------------------------------------------------------------------------
#define NITEMS 256
#define AKH 0
#define AKL 9216
#define AVH 18432
#define AVL 27648
#define ASTG 36864                     // bytes per stage
#define ASM_TOTAL (2*ASTG)
#define SC_LOG2E 0.1803368801111244f   // 0.125 * log2(e)

__global__ __launch_bounds__(256) void attn_kernel(float* __restrict__ out)
{
    extern __shared__ char asmem[];
    __shared__ int s_item, s_done;

    const uint32_t sbA = smem_u32(asmem);
    const int tid   = threadIdx.x;
    const int lane  = tid & 31;
    const int warp  = tid >> 5;
    const int qc    = (lane & 3) * 2;
    const int rql   = lane >> 2;

    // ldmatrix per-lane offset for B tiles (row stride 72 elems = 144B)
    const int brow = (lane & 7) + ((lane >> 4) << 3);
    const int bcol = ((lane >> 3) & 1) << 3;
    const uint32_t bnoff = (uint32_t)(brow*72 + bcol) * 2;

    while (true) {
        __syncthreads();
        if (tid == 0) s_item = atomicAdd(&g_ctr, 1);
        __syncthreads();
        const int item = s_item;
        if (item >= NITEMS) break;

        const int qtile = 15 - (item >> 4);
        const int inner = item & 15;
        const int b     = inner >> 1;
        const int half  = inner & 1;
        const int q0    = qtile * 128;
        const int bq    = b*16 + qtile;

        const int ktbeg = half ? (qtile + 1) : 0;
        const int ktend = half ? (2*qtile + 2) : (qtile + 1);

        auto issueKV = [&](int kt, int stg) {
            const uint32_t ss = sbA + stg*ASTG;
            const size_t kb = (size_t)(b*Tq + kt*64) * Hq;
            const size_t vb = (size_t)(b*Tq + kt*64);
            #pragma unroll
            for (int i = tid; i < 512; i += 256) {
                int t = i >> 3, h0 = (i & 7) * 8;
                uint32_t off = (uint32_t)(t*72 + h0) * 2;
                cp16(ss + AKH + off, &g_kh[kb + (size_t)t*Hq + h0]);
                cp16(ss + AKL + off, &g_kl[kb + (size_t)t*Hq + h0]);
            }
            #pragma unroll
            for (int i = tid; i < 512; i += 256) {
                int h = i >> 3, t0 = (i & 7) * 8;
                uint32_t off = (uint32_t)(h*72 + t0) * 2;
                cp16(ss + AVH + off, &g_vhT[(size_t)h*BT + vb + t0]);
                cp16(ss + AVL + off, &g_vlT[(size_t)h*BT + vb + t0]);
            }
        };

        // Q fragments (hi, lo) in registers
        uint32_t qh[4][4], ql[4][4];
        {
            const size_t rb0 = (size_t)(b*Tq + q0 + warp*16 + rql) * Hq;
            const size_t rb1 = rb0 + 8*Hq;
            #pragma unroll
            for (int ks = 0; ks < 4; ++ks) {
                int k0 = ks*16 + qc;
                qh[ks][0] = *(const uint32_t*)&g_qh[rb0 + k0];
                qh[ks][1] = *(const uint32_t*)&g_qh[rb1 + k0];
                qh[ks][2] = *(const uint32_t*)&g_qh[rb0 + k0 + 8];
                qh[ks][3] = *(const uint32_t*)&g_qh[rb1 + k0 + 8];
                ql[ks][0] = *(const uint32_t*)&g_ql[rb0 + k0];
                ql[ks][1] = *(const uint32_t*)&g_ql[rb1 + k0];
                ql[ks][2] = *(const uint32_t*)&g_ql[rb0 + k0 + 8];
                ql[ks][3] = *(const uint32_t*)&g_ql[rb1 + k0 + 8];
            }
        }

        float o[8][4];
        #pragma unroll
        for (int nt = 0; nt < 8; ++nt)
            #pragma unroll
            for (int j = 0; j < 4; ++j) o[nt][j] = 0.0f;
        float m0r = -1e30f, m1r = -1e30f, l0r = 0.0f, l1r = 0.0f;

        const int row0g = q0 + warp*16 + rql;

        issueKV(ktbeg, 0);
        CP_COMMIT();
        int stg = 0;

        for (int kt = ktbeg; kt < ktend; ++kt) {
            CP_WAIT(0);
            __syncthreads();
            if (kt + 1 < ktend) { issueKV(kt + 1, stg ^ 1); CP_COMMIT(); }

            const uint32_t ss = sbA + stg*ASTG;

            // ---- S = Q K^T ----
            float s[8][4];
            #pragma unroll
            for (int nt = 0; nt < 8; ++nt)
                #pragma unroll
                for (int j = 0; j < 4; ++j) s[nt][j] = 0.0f;

            #pragma unroll
            for (int ks = 0; ks < 4; ++ks) {
                #pragma unroll
                for (int ntp = 0; ntp < 4; ++ntp) {
                    uint32_t bh[4], bl[4];
                    uint32_t a = ss + AKH + (uint32_t)(ntp*16*72 + ks*16)*2 + bnoff;
                    ldsm4(bh, a);
                    ldsm4(bl, a + (AKL - AKH));
                    mma16816(s[2*ntp],   qh[ks], &bh[0]);
                    mma16816(s[2*ntp],   qh[ks], &bl[0]);
                    mma16816(s[2*ntp],   ql[ks], &bh[0]);
                    mma16816(s[2*ntp+1], qh[ks], &bh[2]);
                    mma16816(s[2*ntp+1], qh[ks], &bl[2]);
                    mma16816(s[2*ntp+1], ql[ks], &bh[2]);
                }
            }

            // ---- scale (exp2 domain) + causal mask ----
            const bool need_mask = (kt >= 2*qtile);
            #pragma unroll
            for (int nt = 0; nt < 8; ++nt) {
                const int colg = kt*64 + nt*8 + qc;
                #pragma unroll
                for (int j = 0; j < 4; ++j) {
                    float v = s[nt][j] * SC_LOG2E;
                    if (need_mask) {
                        int cg = colg + (j & 1);
                        int rg = row0g + ((j >> 1) ? 8 : 0);
                        if (cg > rg) v = -1e30f;
                    }
                    s[nt][j] = v;
                }
            }

            // ---- warp-local online softmax (base-2) ----
            float mx0 = -1e30f, mx1 = -1e30f;
            #pragma unroll
            for (int nt = 0; nt < 8; ++nt) {
                mx0 = fmaxf(mx0, fmaxf(s[nt][0], s[nt][1]));
                mx1 = fmaxf(mx1, fmaxf(s[nt][2], s[nt][3]));
            }
            mx0 = fmaxf(mx0, __shfl_xor_sync(0xffffffffu, mx0, 1));
            mx0 = fmaxf(mx0, __shfl_xor_sync(0xffffffffu, mx0, 2));
            mx1 = fmaxf(mx1, __shfl_xor_sync(0xffffffffu, mx1, 1));
            mx1 = fmaxf(mx1, __shfl_xor_sync(0xffffffffu, mx1, 2));
            const float mn0 = fmaxf(m0r, mx0);
            const float mn1 = fmaxf(m1r, mx1);
            const float al0 = ex2(m0r - mn0);
            const float al1 = ex2(m1r - mn1);
            m0r = mn0; m1r = mn1;

            float sum0 = 0.0f, sum1 = 0.0f;
            uint32_t pha[8], phb[8], pla[8], plb[8];
            #pragma unroll
            for (int nt = 0; nt < 8; ++nt) {
                float p0 = ex2(s[nt][0] - mn0);
                float p1 = ex2(s[nt][1] - mn0);
                float p2 = ex2(s[nt][2] - mn1);
                float p3 = ex2(s[nt][3] - mn1);
                sum0 += p0 + p1; sum1 += p2 + p3;
                __nv_bfloat16 h0 = __float2bfloat16(p0);
                __nv_bfloat16 h1 = __float2bfloat16(p1);
                __nv_bfloat16 h2 = __float2bfloat16(p2);
                __nv_bfloat16 h3 = __float2bfloat16(p3);
                __nv_bfloat162 th; th.x = h0; th.y = h1; pha[nt] = *(uint32_t*)&th;
                __nv_bfloat162 tb; tb.x = h2; tb.y = h3; phb[nt] = *(uint32_t*)&tb;
                pla[nt] = pack_bf2(p0 - __bfloat162float(h0), p1 - __bfloat162float(h1));
                plb[nt] = pack_bf2(p2 - __bfloat162float(h2), p3 - __bfloat162float(h3));
            }
            sum0 += __shfl_xor_sync(0xffffffffu, sum0, 1);
            sum0 += __shfl_xor_sync(0xffffffffu, sum0, 2);
            sum1 += __shfl_xor_sync(0xffffffffu, sum1, 1);
            sum1 += __shfl_xor_sync(0xffffffffu, sum1, 2);
            l0r = l0r * al0 + sum0;
            l1r = l1r * al1 + sum1;

            #pragma unroll
            for (int nt = 0; nt < 8; ++nt) {
                o[nt][0] *= al0; o[nt][1] *= al0;
                o[nt][2] *= al1; o[nt][3] *= al1;
            }

            // ---- O += P V ----
            #pragma unroll
            for (int ks = 0; ks < 4; ++ks) {
                uint32_t pah[4] = {pha[2*ks], phb[2*ks], pha[2*ks+1], phb[2*ks+1]};
                uint32_t pal[4] = {pla[2*ks], plb[2*ks], pla[2*ks+1], plb[2*ks+1]};
                #pragma unroll
                for (int ntp = 0; ntp < 4; ++ntp) {
                    uint32_t vh[4], vl[4];
                    uint32_t a = ss + AVH + (uint32_t)(ntp*16*72 + ks*16)*2 + bnoff;
                    ldsm4(vh, a);
                    ldsm4(vl, a + (AVL - AVH));
                    mma16816(o[2*ntp],   pah, &vh[0]);
                    mma16816(o[2*ntp],   pah, &vl[0]);
                    mma16816(o[2*ntp],   pal, &vh[0]);
                    mma16816(o[2*ntp+1], pah, &vh[2]);
                    mma16816(o[2*ntp+1], pah, &vl[2]);
                    mma16816(o[2*ntp+1], pal, &vh[2]);
                }
            }

            stg ^= 1;
        }

        // ---- write unnormalized partials ----
        const int rl0 = warp*16 + rql;
        float* po = &g_po[half][bq][0][0];
        #pragma unroll
        for (int nt = 0; nt < 8; ++nt) {
            const int col = nt*8 + qc;
            *(float2*)&po[(size_t)rl0*64 + col]      = make_float2(o[nt][0], o[nt][1]);
            *(float2*)&po[(size_t)(rl0+8)*64 + col]  = make_float2(o[nt][2], o[nt][3]);
        }
        if ((lane & 3) == 0) {
            g_pml[half][bq][rl0]     = make_float2(m0r, l0r);
            g_pml[half][bq][rl0 + 8] = make_float2(m1r, l1r);
        }

        // ---- last finisher merges (base-2 weights) ----
        __threadfence();
        __syncthreads();
        if (tid == 0) s_done = atomicAdd(&g_flag[bq], 1);
        __syncthreads();
        if (s_done == 1) {
            __threadfence();
            const int r  = tid >> 1;
            const int ch = (tid & 1) * 32;
            float2 A  = g_pml[0][bq][r];
            float2 Bv = g_pml[1][bq][r];
            float m  = fmaxf(A.x, Bv.x);
            float wA = ex2(A.x - m);
            float wB = ex2(Bv.x - m);
            float inv = 1.0f / (wA*A.y + wB*Bv.y);
            const float4* pa = (const float4*)&g_po[0][bq][r][ch];
            const float4* pb = (const float4*)&g_po[1][bq][r][ch];
            float4* pw = (float4*)&out[((size_t)(b*Tq + q0 + r))*64 + ch];
            #pragma unroll
            for (int j = 0; j < 8; ++j) {
                float4 a = pa[j], c = pb[j];
                pw[j] = make_float4((wA*a.x + wB*c.x)*inv, (wA*a.y + wB*c.y)*inv,
                                    (wA*a.z + wB*c.z)*inv, (wA*a.w + wB*c.w)*inv);
            }
        }
    }
}

// ---------------------------------------------------------------------------
extern "C" void kernel_launch(void* const* d_in, const int* in_sizes, int n_in,
                              void* d_out, int out_size)
{
    const float* x  = (const float*)d_in[0];
    const float* Wq = (const float*)d_in[1];
    const float* Wk = (const float*)d_in[2];
    const float* Wv = (const float*)d_in[3];
    float* out = (float*)d_out;

    (void)in_sizes; (void)n_in; (void)out_size;

    wsplit_kernel<<<dim3(16, 3), 256>>>(Wq, Wk, Wv);

    cudaFuncSetAttribute(qkv_gemm_kernel,
                         cudaFuncAttributeMaxDynamicSharedMemorySize, QSM_TOTAL);
    qkv_gemm_kernel<<<128, 256, QSM_TOTAL>>>(x);

    cudaFuncSetAttribute(attn_kernel,
                         cudaFuncAttributeMaxDynamicSharedMemorySize, ASM_TOTAL);
    attn_kernel<<<148, 256, ASM_TOTAL>>>(out);
}

// round 8
// speedup vs baseline: 3.8752x; 1.1027x over previous
#include <cuda_runtime.h>
#include <cuda_bf16.h>
#include <cuda_fp16.h>
#include <cstdint>

#define Bq 8
#define Tq 2048
#define Dq 1024
#define Hq 64
#define BT (Bq*Tq)
#define NQKV 192

// ---------------- device scratch (static globals: allowed) ----------------
__device__ __nv_bfloat16 g_wh[NQKV*Dq];   // transposed: [n][k]
__device__ __nv_bfloat16 g_wl[NQKV*Dq];
__device__ __half g_qh[BT*Hq];            // [t][h] fp16 hi
__device__ __half g_ql[BT*Hq];            // [t][h] fp16 lo
__device__ __half g_k [BT*Hq];            // [t][h] fp16 single
__device__ __half g_vhT[Hq*BT];           // [h][t] fp16 hi
__device__ __half g_vlT[Hq*BT];           // [h][t] fp16 lo
__device__ float  g_po[2][128][128][64];
__device__ float2 g_pml[2][128][128];
__device__ int    g_ctr;
__device__ int    g_flag[128];

// ---------------- helpers ----------------
__device__ __forceinline__ void mma16816(float* c, const uint32_t* a, const uint32_t* b)
{
    asm volatile(
        "mma.sync.aligned.m16n8k16.row.col.f32.bf16.bf16.f32 "
        "{%0,%1,%2,%3}, {%4,%5,%6,%7}, {%8,%9}, {%0,%1,%2,%3};"
        : "+f"(c[0]), "+f"(c[1]), "+f"(c[2]), "+f"(c[3])
        : "r"(a[0]), "r"(a[1]), "r"(a[2]), "r"(a[3]), "r"(b[0]), "r"(b[1]));
}

__device__ __forceinline__ void mma_f16(float* c, const uint32_t* a, const uint32_t* b)
{
    asm volatile(
        "mma.sync.aligned.m16n8k16.row.col.f32.f16.f16.f32 "
        "{%0,%1,%2,%3}, {%4,%5,%6,%7}, {%8,%9}, {%0,%1,%2,%3};"
        : "+f"(c[0]), "+f"(c[1]), "+f"(c[2]), "+f"(c[3])
        : "r"(a[0]), "r"(a[1]), "r"(a[2]), "r"(a[3]), "r"(b[0]), "r"(b[1]));
}

__device__ __forceinline__ void ldsm4(uint32_t* r, uint32_t addr)
{
    asm volatile("ldmatrix.sync.aligned.m8n8.x4.shared.b16 {%0,%1,%2,%3}, [%4];"
        : "=r"(r[0]), "=r"(r[1]), "=r"(r[2]), "=r"(r[3]) : "r"(addr));
}

__device__ __forceinline__ float ex2(float x)
{
    float y;
    asm("ex2.approx.f32 %0, %1;" : "=f"(y) : "f"(x));
    return y;
}

__device__ __forceinline__ uint32_t pack_h2(float a, float b)
{
    __half2 t = __floats2half2_rn(a, b);
    return *(uint32_t*)&t;
}

__device__ __forceinline__ uint32_t smem_u32(const void* p) {
    uint32_t a;
    asm("{ .reg .u64 t; cvta.to.shared.u64 t, %1; cvt.u32.u64 %0, t; }"
        : "=r"(a) : "l"(p));
    return a;
}

__device__ __forceinline__ void cp16(uint32_t d, const void* s) {
    asm volatile("cp.async.cg.shared.global [%0], [%1], 16;" :: "r"(d), "l"(s) : "memory");
}
#define CP_COMMIT() asm volatile("cp.async.commit_group;" ::: "memory")
#define CP_WAIT(n)  asm volatile("cp.async.wait_group %0;" :: "n"(n) : "memory")

// ---------------------------------------------------------------------------
// Kernel 0: W -> transposed split bf16; resets queue state.
// ---------------------------------------------------------------------------
__global__ __launch_bounds__(256) void wsplit_kernel(
    const float* __restrict__ Wq, const float* __restrict__ Wk, const float* __restrict__ Wv)
{
    __shared__ float S[64][65];
    const int kb  = blockIdx.x;
    const int src = blockIdx.y;
    const int tid = threadIdx.x;

    if (kb == 0 && src == 0) {
        if (tid == 0) g_ctr = 0;
        if (tid < 128) g_flag[tid] = 0;
    }

    const float* W = (src == 0) ? Wq : (src == 1) ? Wk : Wv;

    #pragma unroll
    for (int i = tid; i < 1024; i += 256) {
        int kk = i >> 4, h4 = (i & 15) * 4;
        float4 v = *(const float4*)&W[(size_t)(kb*64 + kk)*64 + h4];
        S[kk][h4] = v.x; S[kk][h4+1] = v.y; S[kk][h4+2] = v.z; S[kk][h4+3] = v.w;
    }
    __syncthreads();

    const int n  = tid >> 2;
    const int kq = (tid & 3) * 16;
    const size_t go = (size_t)(src*64 + n)*Dq + kb*64 + kq;
    #pragma unroll
    for (int j = 0; j < 16; j += 2) {
        float v0 = S[kq + j][n], v1 = S[kq + j + 1][n];
        __nv_bfloat16 h0 = __float2bfloat16(v0);
        __nv_bfloat16 h1 = __float2bfloat16(v1);
        __nv_bfloat162 hh; hh.x = h0; hh.y = h1;
        __nv_bfloat162 ll;
        ll.x = __float2bfloat16(v0 - __bfloat162float(h0));
        ll.y = __float2bfloat16(v1 - __bfloat162float(h1));
        *(__nv_bfloat162*)&g_wh[go + j] = hh;
        *(__nv_bfloat162*)&g_wl[go + j] = ll;
    }
}

// ---------------------------------------------------------------------------
// Kernel 1: fused split + QKV GEMM (bf16 x3, unchanged math). Epilogue now
// emits fp16: q split (hi,lo), k single, v split transposed.
// ---------------------------------------------------------------------------
#define QXH 0
#define QXL 10240
#define QWH 20480
#define QWL 35840
#define QST 51200
#define QSM_TOTAL (2*QST)

__global__ __launch_bounds__(256) void qkv_gemm_kernel(const float* __restrict__ x)
{
    extern __shared__ char smem[];
    const uint32_t sb = smem_u32(smem);

    const int tid  = threadIdx.x;
    const int lane = tid & 31;
    const int warp = tid >> 5;
    const int m0   = blockIdx.x * 128;
    const int wm   = warp & 1;
    const int wn   = warp >> 1;
    const int rql  = lane >> 2;
    const int qc   = (lane & 3) * 2;

    const int arow = (lane & 7) + (((lane >> 3) & 1) << 3);
    const int acol = (lane >> 4) << 3;
    const uint32_t axoff = (uint32_t)(arow*40 + acol) * 2;
    const int brow = (lane & 7) + ((lane >> 4) << 3);
    const int bcol = ((lane >> 3) & 1) << 3;
    const uint32_t bxoff = (uint32_t)(brow*40 + bcol) * 2;

    float c[4][6][4];
    #pragma unroll
    for (int mt = 0; mt < 4; ++mt)
        #pragma unroll
        for (int nt = 0; nt < 6; ++nt)
            #pragma unroll
            for (int j = 0; j < 4; ++j) c[mt][nt][j] = 0.0f;

    float4 xr[4];

    auto loadX = [&](int kc) {
        #pragma unroll
        for (int j = 0; j < 4; ++j) {
            int i = tid + j*256;
            int r = i >> 3, c4 = i & 7;
            xr[j] = *(const float4*)&x[(size_t)(m0 + r)*Dq + kc + c4*4];
        }
    };
    auto stsX = [&](int stg) {
        char* s = smem + stg*QST;
        #pragma unroll
        for (int j = 0; j < 4; ++j) {
            int i = tid + j*256;
            int r = i >> 3, c4 = i & 7;
            float4 v = xr[j];
            __nv_bfloat16 h0 = __float2bfloat16(v.x);
            __nv_bfloat16 h1 = __float2bfloat16(v.y);
            __nv_bfloat16 h2 = __float2bfloat16(v.z);
            __nv_bfloat16 h3 = __float2bfloat16(v.w);
            __nv_bfloat162 ha; ha.x = h0; ha.y = h1;
            __nv_bfloat162 hb; hb.x = h2; hb.y = h3;
            __nv_bfloat162 la; la.x = __float2bfloat16(v.x - __bfloat162float(h0));
                               la.y = __float2bfloat16(v.y - __bfloat162float(h1));
            __nv_bfloat162 lb; lb.x = __float2bfloat16(v.z - __bfloat162float(h2));
                               lb.y = __float2bfloat16(v.w - __bfloat162float(h3));
            int off = (r*40 + c4*4) * 2;
            *(__nv_bfloat162*)(s + QXH + off)     = ha;
            *(__nv_bfloat162*)(s + QXH + off + 4) = hb;
            *(__nv_bfloat162*)(s + QXL + off)     = la;
            *(__nv_bfloat162*)(s + QXL + off + 4) = lb;
        }
    };
    auto cpW = [&](int kc, int stg) {
        uint32_t s = sb + stg*QST;
        #pragma unroll
        for (int i = tid; i < 768; i += 256) {
            int r = i >> 2, c16 = (i & 3) * 8;
            uint32_t off = (uint32_t)(r*40 + c16) * 2;
            cp16(s + QWH + off, &g_wh[(size_t)r*Dq + kc + c16]);
            cp16(s + QWL + off, &g_wl[(size_t)r*Dq + kc + c16]);
        }
    };

    loadX(0);
    cpW(0, 0);
    CP_COMMIT();
    stsX(0);
    CP_WAIT(0);
    __syncthreads();

    for (int i = 0; i < 32; ++i) {
        const int cur = i & 1, nxt = cur ^ 1;
        const int kc = i * 32;
        if (i < 31) {
            cpW(kc + 32, nxt);
            CP_COMMIT();
            loadX(kc + 32);
        }

        const uint32_t sc = sb + cur*QST;

        #pragma unroll
        for (int ks = 0; ks < 2; ++ks) {
            const int k0 = ks*16;
            uint32_t ah[4][4], al_[4][4];
            #pragma unroll
            for (int mt = 0; mt < 4; ++mt) {
                uint32_t a = sc + QXH + (uint32_t)((wm*64 + mt*16)*40 + k0)*2 + axoff;
                ldsm4(ah[mt], a);
                ldsm4(al_[mt], a + (QXL - QXH));
            }
            #pragma unroll
            for (int ntp = 0; ntp < 3; ++ntp) {
                uint32_t bh[4], bl[4];
                uint32_t bA = sc + QWH + (uint32_t)((wn*48 + ntp*16)*40 + k0)*2 + bxoff;
                ldsm4(bh, bA);
                ldsm4(bl, bA + (QWL - QWH));
                #pragma unroll
                for (int mt = 0; mt < 4; ++mt) {
                    mma16816(c[mt][2*ntp],   ah[mt], &bh[0]);
                    mma16816(c[mt][2*ntp],   ah[mt], &bl[0]);
                    mma16816(c[mt][2*ntp],   al_[mt], &bh[0]);
                    mma16816(c[mt][2*ntp+1], ah[mt], &bh[2]);
                    mma16816(c[mt][2*ntp+1], ah[mt], &bl[2]);
                    mma16816(c[mt][2*ntp+1], al_[mt], &bh[2]);
                }
            }
        }

        if (i < 31) stsX(nxt);
        CP_WAIT(0);
        __syncthreads();
    }

    // epilogue: fp32 -> fp16 scatter (q split, k single, v split transposed)
    #pragma unroll
    for (int mt = 0; mt < 4; ++mt) {
        #pragma unroll
        for (int nt = 0; nt < 6; ++nt) {
            const int gc = wn*48 + nt*8 + qc;
            #pragma unroll
            for (int hf = 0; hf < 2; ++hf) {
                const int row = m0 + wm*64 + mt*16 + rql + hf*8;
                float v0 = c[mt][nt][hf*2], v1 = c[mt][nt][hf*2 + 1];
                if (gc < 64) {
                    __half h0 = __float2half_rn(v0);
                    __half h1 = __float2half_rn(v1);
                    __half2 hh; hh.x = h0; hh.y = h1;
                    __half2 ll;
                    ll.x = __float2half_rn(v0 - __half2float(h0));
                    ll.y = __float2half_rn(v1 - __half2float(h1));
                    *(__half2*)&g_qh[(size_t)row*Hq + gc] = hh;
                    *(__half2*)&g_ql[(size_t)row*Hq + gc] = ll;
                } else if (gc < 128) {
                    *(__half2*)&g_k[(size_t)row*Hq + gc - 64] = __floats2half2_rn(v0, v1);
                } else {
                    const int h = gc - 128;
                    __half h0 = __float2half_rn(v0);
                    __half h1 = __float2half_rn(v1);
                    g_vhT[(size_t) h   *BT + row] = h0;
                    g_vhT[(size_t)(h+1)*BT + row] = h1;
                    g_vlT[(size_t) h   *BT + row] = __float2half_rn(v0 - __half2float(h0));
                    g_vlT[(size_t)(h+1)*BT + row] = __float2half_rn(v1 - __half2float(h1));
                }
            }
        }
    }
}

// ---------------------------------------------------------------------------
// Kernel 2: persistent split-K flash attention + fused merge, fp16 2-product.
// S = (Qh+Ql)·K ; O += P·(Vh+Vl). Double-buffered, ldmatrix, exp2 softmax.
// ---------------------------------------------------------------------------
#define NITEMS 256
#define AK  0
#define AVH 9216
#define AVL 18432
#define ASTG 27648
#define ASM_TOTAL (2*ASTG)
#define SC_LOG2E 0.1803368801111244f   // 0.125 * log2(e)

__global__ __launch_bounds__(256) void attn_kernel(float* __restrict__ out)
{
    extern __shared__ char asmem[];
    __shared__ int s_item, s_done;

    const uint32_t sbA = smem_u32(asmem);
    const int tid   = threadIdx.x;
    const int lane  = tid & 31;
    const int warp  = tid >> 5;
    const int qc    = (lane & 3) * 2;
    const int rql   = lane >> 2;

    const int brow = (lane & 7) + ((lane >> 4) << 3);
    const int bcol = ((lane >> 3) & 1) << 3;
    const uint32_t bnoff = (uint32_t)(brow*72 + bcol) * 2;

    while (true) {
        __syncthreads();
        if (tid == 0) s_item = atomicAdd(&g_ctr, 1);
        __syncthreads();
        const int item = s_item;
        if (item >= NITEMS) break;

        const int qtile = 15 - (item >> 4);
        const int inner = item & 15;
        const int b     = inner >> 1;
        const int half  = inner & 1;
        const int q0    = qtile * 128;
        const int bq    = b*16 + qtile;

        const int ktbeg = half ? (qtile + 1) : 0;
        const int ktend = half ? (2*qtile + 2) : (qtile + 1);

        auto issueKV = [&](int kt, int stg) {
            const uint32_t ss = sbA + stg*ASTG;
            const size_t kb = (size_t)(b*Tq + kt*64) * Hq;
            const size_t vb = (size_t)(b*Tq + kt*64);
            #pragma unroll
            for (int i = tid; i < 512; i += 256) {
                int t = i >> 3, h0 = (i & 7) * 8;
                cp16(ss + AK + (uint32_t)(t*72 + h0)*2, &g_k[kb + (size_t)t*Hq + h0]);
            }
            #pragma unroll
            for (int i = tid; i < 512; i += 256) {
                int h = i >> 3, t0 = (i & 7) * 8;
                uint32_t off = (uint32_t)(h*72 + t0) * 2;
                cp16(ss + AVH + off, &g_vhT[(size_t)h*BT + vb + t0]);
                cp16(ss + AVL + off, &g_vlT[(size_t)h*BT + vb + t0]);
            }
        };

        // Q fragments (fp16 hi, lo) in registers
        uint32_t qh[4][4], ql[4][4];
        {
            const size_t rb0 = (size_t)(b*Tq + q0 + warp*16 + rql) * Hq;
            const size_t rb1 = rb0 + 8*Hq;
            #pragma unroll
            for (int ks = 0; ks < 4; ++ks) {
                int k0 = ks*16 + qc;
                qh[ks][0] = *(const uint32_t*)&g_qh[rb0 + k0];
                qh[ks][1] = *(const uint32_t*)&g_qh[rb1 + k0];
                qh[ks][2] = *(const uint32_t*)&g_qh[rb0 + k0 + 8];
                qh[ks][3] = *(const uint32_t*)&g_qh[rb1 + k0 + 8];
                ql[ks][0] = *(const uint32_t*)&g_ql[rb0 + k0];
                ql[ks][1] = *(const uint32_t*)&g_ql[rb1 + k0];
                ql[ks][2] = *(const uint32_t*)&g_ql[rb0 + k0 + 8];
                ql[ks][3] = *(const uint32_t*)&g_ql[rb1 + k0 + 8];
            }
        }

        float o[8][4];
        #pragma unroll
        for (int nt = 0; nt < 8; ++nt)
            #pragma unroll
            for (int j = 0; j < 4; ++j) o[nt][j] = 0.0f;
        float m0r = -1e30f, m1r = -1e30f, l0r = 0.0f, l1r = 0.0f;

        const int row0g = q0 + warp*16 + rql;

        issueKV(ktbeg, 0);
        CP_COMMIT();
        int stg = 0;

        for (int kt = ktbeg; kt < ktend; ++kt) {
            CP_WAIT(0);
            __syncthreads();
            if (kt + 1 < ktend) { issueKV(kt + 1, stg ^ 1); CP_COMMIT(); }

            const uint32_t ss = sbA + stg*ASTG;

            // ---- S = (Qh + Ql) K^T ----
            float s[8][4];
            #pragma unroll
            for (int nt = 0; nt < 8; ++nt)
                #pragma unroll
                for (int j = 0; j < 4; ++j) s[nt][j] = 0.0f;

            #pragma unroll
            for (int ks = 0; ks < 4; ++ks) {
                #pragma unroll
                for (int ntp = 0; ntp < 4; ++ntp) {
                    uint32_t kf[4];
                    ldsm4(kf, ss + AK + (uint32_t)(ntp*16*72 + ks*16)*2 + bnoff);
                    mma_f16(s[2*ntp],   qh[ks], &kf[0]);
                    mma_f16(s[2*ntp],   ql[ks], &kf[0]);
                    mma_f16(s[2*ntp+1], qh[ks], &kf[2]);
                    mma_f16(s[2*ntp+1], ql[ks], &kf[2]);
                }
            }

            // ---- scale (exp2 domain) + causal mask ----
            const bool need_mask = (kt >= 2*qtile);
            #pragma unroll
            for (int nt = 0; nt < 8; ++nt) {
                const int colg = kt*64 + nt*8 + qc;
                #pragma unroll
                for (int j = 0; j < 4; ++j) {
                    float v = s[nt][j] * SC_LOG2E;
                    if (need_mask) {
                        int cg = colg + (j & 1);
                        int rg = row0g + ((j >> 1) ? 8 : 0);
                        if (cg > rg) v = -1e30f;
                    }
                    s[nt][j] = v;
                }
            }

            // ---- warp-local online softmax (base-2) ----
            float mx0 = -1e30f, mx1 = -1e30f;
            #pragma unroll
            for (int nt = 0; nt < 8; ++nt) {
                mx0 = fmaxf(mx0, fmaxf(s[nt][0], s[nt][1]));
                mx1 = fmaxf(mx1, fmaxf(s[nt][2], s[nt][3]));
            }
            mx0 = fmaxf(mx0, __shfl_xor_sync(0xffffffffu, mx0, 1));
            mx0 = fmaxf(mx0, __shfl_xor_sync(0xffffffffu, mx0, 2));
            mx1 = fmaxf(mx1, __shfl_xor_sync(0xffffffffu, mx1, 1));
            mx1 = fmaxf(mx1, __shfl_xor_sync(0xffffffffu, mx1, 2));
            const float mn0 = fmaxf(m0r, mx0);
            const float mn1 = fmaxf(m1r, mx1);
            const float al0 = ex2(m0r - mn0);
            const float al1 = ex2(m1r - mn1);
            m0r = mn0; m1r = mn1;

            float sum0 = 0.0f, sum1 = 0.0f;
            uint32_t pha[8], phb[8];
            #pragma unroll
            for (int nt = 0; nt < 8; ++nt) {
                float p0 = ex2(s[nt][0] - mn0);
                float p1 = ex2(s[nt][1] - mn0);
                float p2 = ex2(s[nt][2] - mn1);
                float p3 = ex2(s[nt][3] - mn1);
                sum0 += p0 + p1; sum1 += p2 + p3;
                pha[nt] = pack_h2(p0, p1);
                phb[nt] = pack_h2(p2, p3);
            }
            sum0 += __shfl_xor_sync(0xffffffffu, sum0, 1);
            sum0 += __shfl_xor_sync(0xffffffffu, sum0, 2);
            sum1 += __shfl_xor_sync(0xffffffffu, sum1, 1);
            sum1 += __shfl_xor_sync(0xffffffffu, sum1, 2);
            l0r = l0r * al0 + sum0;
            l1r = l1r * al1 + sum1;

            #pragma unroll
            for (int nt = 0; nt < 8; ++nt) {
                o[nt][0] *= al0; o[nt][1] *= al0;
                o[nt][2] *= al1; o[nt][3] *= al1;
            }

            // ---- O += P (Vh + Vl) ----
            #pragma unroll
            for (int ks = 0; ks < 4; ++ks) {
                uint32_t pa[4] = {pha[2*ks], phb[2*ks], pha[2*ks+1], phb[2*ks+1]};
                #pragma unroll
                for (int ntp = 0; ntp < 4; ++ntp) {
                    uint32_t vh[4], vl[4];
                    uint32_t a = ss + AVH + (uint32_t)(ntp*16*72 + ks*16)*2 + bnoff;
                    ldsm4(vh, a);
                    ldsm4(vl, a + (AVL - AVH));
                    mma_f16(o[2*ntp],   pa, &vh[0]);
                    mma_f16(o[2*ntp],   pa, &vl[0]);
                    mma_f16(o[2*ntp+1], pa, &vh[2]);
                    mma_f16(o[2*ntp+1], pa, &vl[2]);
                }
            }

            stg ^= 1;
        }

        // ---- write unnormalized partials ----
        const int rl0 = warp*16 + rql;
        float* po = &g_po[half][bq][0][0];
        #pragma unroll
        for (int nt = 0; nt < 8; ++nt) {
            const int col = nt*8 + qc;
            *(float2*)&po[(size_t)rl0*64 + col]      = make_float2(o[nt][0], o[nt][1]);
            *(float2*)&po[(size_t)(rl0+8)*64 + col]  = make_float2(o[nt][2], o[nt][3]);
        }
        if ((lane & 3) == 0) {
            g_pml[half][bq][rl0]     = make_float2(m0r, l0r);
            g_pml[half][bq][rl0 + 8] = make_float2(m1r, l1r);
        }

        // ---- last finisher merges (base-2 weights) ----
        __threadfence();
        __syncthreads();
        if (tid == 0) s_done = atomicAdd(&g_flag[bq], 1);
        __syncthreads();
        if (s_done == 1) {
            __threadfence();
            const int r  = tid >> 1;
            const int ch = (tid & 1) * 32;
            float2 A  = g_pml[0][bq][r];
            float2 Bv = g_pml[1][bq][r];
            float m  = fmaxf(A.x, Bv.x);
            float wA = ex2(A.x - m);
            float wB = ex2(Bv.x - m);
            float inv = 1.0f / (wA*A.y + wB*Bv.y);
            const float4* pa = (const float4*)&g_po[0][bq][r][ch];
            const float4* pb = (const float4*)&g_po[1][bq][r][ch];
            float4* pw = (float4*)&out[((size_t)(b*Tq + q0 + r))*64 + ch];
            #pragma unroll
            for (int j = 0; j < 8; ++j) {
                float4 a = pa[j], c = pb[j];
                pw[j] = make_float4((wA*a.x + wB*c.x)*inv, (wA*a.y + wB*c.y)*inv,
                                    (wA*a.z + wB*c.z)*inv, (wA*a.w + wB*c.w)*inv);
            }
        }
    }
}

// ---------------------------------------------------------------------------
extern "C" void kernel_launch(void* const* d_in, const int* in_sizes, int n_in,
                              void* d_out, int out_size)
{
    const float* x  = (const float*)d_in[0];
    const float* Wq = (const float*)d_in[1];
    const float* Wk = (const float*)d_in[2];
    const float* Wv = (const float*)d_in[3];
    float* out = (float*)d_out;

    (void)in_sizes; (void)n_in; (void)out_size;

    wsplit_kernel<<<dim3(16, 3), 256>>>(Wq, Wk, Wv);

    cudaFuncSetAttribute(qkv_gemm_kernel,
                         cudaFuncAttributeMaxDynamicSharedMemorySize, QSM_TOTAL);
    qkv_gemm_kernel<<<128, 256, QSM_TOTAL>>>(x);

    cudaFuncSetAttribute(attn_kernel,
                         cudaFuncAttributeMaxDynamicSharedMemorySize, ASM_TOTAL);
    attn_kernel<<<148, 256, ASM_TOTAL>>>(out);
}

// round 9
// speedup vs baseline: 4.7595x; 1.2282x over previous
#include <cuda_runtime.h>
#include <cuda_bf16.h>
#include <cuda_fp16.h>
#include <cstdint>

#define Bq 8
#define Tq 2048
#define Dq 1024
#define Hq 64
#define BT (Bq*Tq)
#define NQKV 192

// ---------------- device scratch (static globals: allowed) ----------------
__device__ __half g_wf[NQKV*Dq];          // transposed: [n][k], fp16 single
__device__ __half g_qh[BT*Hq];            // [t][h] fp16 hi
__device__ __half g_ql[BT*Hq];            // [t][h] fp16 lo
__device__ __half g_k [BT*Hq];            // [t][h] fp16 single
__device__ __half g_vhT[Hq*BT];           // [h][t] fp16 hi
__device__ __half g_vlT[Hq*BT];           // [h][t] fp16 lo
__device__ float  g_po[2][128][128][64];
__device__ float2 g_pml[2][128][128];
__device__ int    g_ctr;
__device__ int    g_flag[128];

// ---------------- helpers ----------------
__device__ __forceinline__ void mma_f16(float* c, const uint32_t* a, const uint32_t* b)
{
    asm volatile(
        "mma.sync.aligned.m16n8k16.row.col.f32.f16.f16.f32 "
        "{%0,%1,%2,%3}, {%4,%5,%6,%7}, {%8,%9}, {%0,%1,%2,%3};"
        : "+f"(c[0]), "+f"(c[1]), "+f"(c[2]), "+f"(c[3])
        : "r"(a[0]), "r"(a[1]), "r"(a[2]), "r"(a[3]), "r"(b[0]), "r"(b[1]));
}

__device__ __forceinline__ void ldsm4(uint32_t* r, uint32_t addr)
{
    asm volatile("ldmatrix.sync.aligned.m8n8.x4.shared.b16 {%0,%1,%2,%3}, [%4];"
        : "=r"(r[0]), "=r"(r[1]), "=r"(r[2]), "=r"(r[3]) : "r"(addr));
}

__device__ __forceinline__ float ex2(float x)
{
    float y;
    asm("ex2.approx.f32 %0, %1;" : "=f"(y) : "f"(x));
    return y;
}

__device__ __forceinline__ uint32_t pack_h2(float a, float b)
{
    __half2 t = __floats2half2_rn(a, b);
    return *(uint32_t*)&t;
}

__device__ __forceinline__ uint32_t smem_u32(const void* p) {
    uint32_t a;
    asm("{ .reg .u64 t; cvta.to.shared.u64 t, %1; cvt.u32.u64 %0, t; }"
        : "=r"(a) : "l"(p));
    return a;
}

__device__ __forceinline__ void cp16(uint32_t d, const void* s) {
    asm volatile("cp.async.cg.shared.global [%0], [%1], 16;" :: "r"(d), "l"(s) : "memory");
}
#define CP_COMMIT() asm volatile("cp.async.commit_group;" ::: "memory")
#define CP_WAIT(n)  asm volatile("cp.async.wait_group %0;" :: "n"(n) : "memory")

// ---------------------------------------------------------------------------
// Kernel 0: W -> transposed fp16 single; resets queue state.
// ---------------------------------------------------------------------------
__global__ __launch_bounds__(256) void wsplit_kernel(
    const float* __restrict__ Wq, const float* __restrict__ Wk, const float* __restrict__ Wv)
{
    __shared__ float S[64][65];
    const int kb  = blockIdx.x;
    const int src = blockIdx.y;
    const int tid = threadIdx.x;

    if (kb == 0 && src == 0) {
        if (tid == 0) g_ctr = 0;
        if (tid < 128) g_flag[tid] = 0;
    }

    const float* W = (src == 0) ? Wq : (src == 1) ? Wk : Wv;

    #pragma unroll
    for (int i = tid; i < 1024; i += 256) {
        int kk = i >> 4, h4 = (i & 15) * 4;
        float4 v = *(const float4*)&W[(size_t)(kb*64 + kk)*64 + h4];
        S[kk][h4] = v.x; S[kk][h4+1] = v.y; S[kk][h4+2] = v.z; S[kk][h4+3] = v.w;
    }
    __syncthreads();

    const int n  = tid >> 2;
    const int kq = (tid & 3) * 16;
    const size_t go = (size_t)(src*64 + n)*Dq + kb*64 + kq;
    #pragma unroll
    for (int j = 0; j < 16; j += 2) {
        *(__half2*)&g_wf[go + j] = __floats2half2_rn(S[kq + j][n], S[kq + j + 1][n]);
    }
}

// ---------------------------------------------------------------------------
// Kernel 1: fused split + QKV GEMM, fp16 2-product: C = (Xh + Xl) @ Wf^T.
// Double-buffered, ldmatrix fragments. grid = 128 M-tiles, 256 threads.
// ---------------------------------------------------------------------------
#define QXH 0
#define QXL 10240
#define QW  20480
#define QST 35840
#define QSM_TOTAL (2*QST)

__global__ __launch_bounds__(256) void qkv_gemm_kernel(const float* __restrict__ x)
{
    extern __shared__ char smem[];
    const uint32_t sb = smem_u32(smem);

    const int tid  = threadIdx.x;
    const int lane = tid & 31;
    const int warp = tid >> 5;
    const int m0   = blockIdx.x * 128;
    const int wm   = warp & 1;
    const int wn   = warp >> 1;
    const int rql  = lane >> 2;
    const int qc   = (lane & 3) * 2;

    const int arow = (lane & 7) + (((lane >> 3) & 1) << 3);
    const int acol = (lane >> 4) << 3;
    const uint32_t axoff = (uint32_t)(arow*40 + acol) * 2;
    const int brow = (lane & 7) + ((lane >> 4) << 3);
    const int bcol = ((lane >> 3) & 1) << 3;
    const uint32_t bxoff = (uint32_t)(brow*40 + bcol) * 2;

    float c[4][6][4];
    #pragma unroll
    for (int mt = 0; mt < 4; ++mt)
        #pragma unroll
        for (int nt = 0; nt < 6; ++nt)
            #pragma unroll
            for (int j = 0; j < 4; ++j) c[mt][nt][j] = 0.0f;

    float4 xr[4];

    auto loadX = [&](int kc) {
        #pragma unroll
        for (int j = 0; j < 4; ++j) {
            int i = tid + j*256;
            int r = i >> 3, c4 = i & 7;
            xr[j] = *(const float4*)&x[(size_t)(m0 + r)*Dq + kc + c4*4];
        }
    };
    auto stsX = [&](int stg) {
        char* s = smem + stg*QST;
        #pragma unroll
        for (int j = 0; j < 4; ++j) {
            int i = tid + j*256;
            int r = i >> 3, c4 = i & 7;
            float4 v = xr[j];
            __half h0 = __float2half_rn(v.x);
            __half h1 = __float2half_rn(v.y);
            __half h2 = __float2half_rn(v.z);
            __half h3 = __float2half_rn(v.w);
            __half2 ha; ha.x = h0; ha.y = h1;
            __half2 hb; hb.x = h2; hb.y = h3;
            __half2 la; la.x = __float2half_rn(v.x - __half2float(h0));
                        la.y = __float2half_rn(v.y - __half2float(h1));
            __half2 lb; lb.x = __float2half_rn(v.z - __half2float(h2));
                        lb.y = __float2half_rn(v.w - __half2float(h3));
            int off = (r*40 + c4*4) * 2;
            *(__half2*)(s + QXH + off)     = ha;
            *(__half2*)(s + QXH + off + 4) = hb;
            *(__half2*)(s + QXL + off)     = la;
            *(__half2*)(s + QXL + off + 4) = lb;
        }
    };
    auto cpW = [&](int kc, int stg) {
        uint32_t s = sb + stg*QST;
        #pragma unroll
        for (int i = tid; i < 768; i += 256) {
            int r = i >> 2, c16 = (i & 3) * 8;
            uint32_t off = (uint32_t)(r*40 + c16) * 2;
            cp16(s + QW + off, &g_wf[(size_t)r*Dq + kc + c16]);
        }
    };

    loadX(0);
    cpW(0, 0);
    CP_COMMIT();
    stsX(0);
    CP_WAIT(0);
    __syncthreads();

    for (int i = 0; i < 32; ++i) {
        const int cur = i & 1, nxt = cur ^ 1;
        const int kc = i * 32;
        if (i < 31) {
            cpW(kc + 32, nxt);
            CP_COMMIT();
            loadX(kc + 32);
        }

        const uint32_t sc = sb + cur*QST;

        #pragma unroll
        for (int ks = 0; ks < 2; ++ks) {
            const int k0 = ks*16;
            uint32_t ah[4][4], al_[4][4];
            #pragma unroll
            for (int mt = 0; mt < 4; ++mt) {
                uint32_t a = sc + QXH + (uint32_t)((wm*64 + mt*16)*40 + k0)*2 + axoff;
                ldsm4(ah[mt], a);
                ldsm4(al_[mt], a + (QXL - QXH));
            }
            #pragma unroll
            for (int ntp = 0; ntp < 3; ++ntp) {
                uint32_t wf[4];
                ldsm4(wf, sc + QW + (uint32_t)((wn*48 + ntp*16)*40 + k0)*2 + bxoff);
                #pragma unroll
                for (int mt = 0; mt < 4; ++mt) {
                    mma_f16(c[mt][2*ntp],   ah[mt],  &wf[0]);
                    mma_f16(c[mt][2*ntp],   al_[mt], &wf[0]);
                    mma_f16(c[mt][2*ntp+1], ah[mt],  &wf[2]);
                    mma_f16(c[mt][2*ntp+1], al_[mt], &wf[2]);
                }
            }
        }

        if (i < 31) stsX(nxt);
        CP_WAIT(0);
        __syncthreads();
    }

    // epilogue: fp32 -> fp16 scatter (q split, k single, v split transposed)
    #pragma unroll
    for (int mt = 0; mt < 4; ++mt) {
        #pragma unroll
        for (int nt = 0; nt < 6; ++nt) {
            const int gc = wn*48 + nt*8 + qc;
            #pragma unroll
            for (int hf = 0; hf < 2; ++hf) {
                const int row = m0 + wm*64 + mt*16 + rql + hf*8;
                float v0 = c[mt][nt][hf*2], v1 = c[mt][nt][hf*2 + 1];
                if (gc < 64) {
                    __half h0 = __float2half_rn(v0);
                    __half h1 = __float2half_rn(v1);
                    __half2 hh; hh.x = h0; hh.y = h1;
                    __half2 ll;
                    ll.x = __float2half_rn(v0 - __half2float(h0));
                    ll.y = __float2half_rn(v1 - __half2float(h1));
                    *(__half2*)&g_qh[(size_t)row*Hq + gc] = hh;
                    *(__half2*)&g_ql[(size_t)row*Hq + gc] = ll;
                } else if (gc < 128) {
                    *(__half2*)&g_k[(size_t)row*Hq + gc - 64] = __floats2half2_rn(v0, v1);
                } else {
                    const int h = gc - 128;
                    __half h0 = __float2half_rn(v0);
                    __half h1 = __float2half_rn(v1);
                    g_vhT[(size_t) h   *BT + row] = h0;
                    g_vhT[(size_t)(h+1)*BT + row] = h1;
                    g_vlT[(size_t) h   *BT + row] = __float2half_rn(v0 - __half2float(h0));
                    g_vlT[(size_t)(h+1)*BT + row] = __float2half_rn(v1 - __half2float(h1));
                }
            }
        }
    }
}

// ---------------------------------------------------------------------------
// Kernel 2: persistent split-K flash attention + fused merge, fp16 2-product.
// S = (Qh+Ql)·K ; O += P·(Vh+Vl). Double-buffered, ldmatrix, exp2 softmax.
// ---------------------------------------------------------------------------
#define NITEMS 256
#define AK  0
#define AVH 9216
#define AVL 18432
#define ASTG 27648
#define ASM_TOTAL (2*ASTG)
#define SC_LOG2E 0.1803368801111244f   // 0.125 * log2(e)

__global__ __launch_bounds__(256) void attn_kernel(float* __restrict__ out)
{
    extern __shared__ char asmem[];
    __shared__ int s_item, s_done;

    const uint32_t sbA = smem_u32(asmem);
    const int tid   = threadIdx.x;
    const int lane  = tid & 31;
    const int warp  = tid >> 5;
    const int qc    = (lane & 3) * 2;
    const int rql   = lane >> 2;

    const int brow = (lane & 7) + ((lane >> 4) << 3);
    const int bcol = ((lane >> 3) & 1) << 3;
    const uint32_t bnoff = (uint32_t)(brow*72 + bcol) * 2;

    while (true) {
        __syncthreads();
        if (tid == 0) s_item = atomicAdd(&g_ctr, 1);
        __syncthreads();
        const int item = s_item;
        if (item >= NITEMS) break;

        const int qtile = 15 - (item >> 4);
        const int inner = item & 15;
        const int b     = inner >> 1;
        const int half  = inner & 1;
        const int q0    = qtile * 128;
        const int bq    = b*16 + qtile;

        const int ktbeg = half ? (qtile + 1) : 0;
        const int ktend = half ? (2*qtile + 2) : (qtile + 1);

        auto issueKV = [&](int kt, int stg) {
            const uint32_t ss = sbA + stg*ASTG;
            const size_t kb = (size_t)(b*Tq + kt*64) * Hq;
            const size_t vb = (size_t)(b*Tq + kt*64);
            #pragma unroll
            for (int i = tid; i < 512; i += 256) {
                int t = i >> 3, h0 = (i & 7) * 8;
                cp16(ss + AK + (uint32_t)(t*72 + h0)*2, &g_k[kb + (size_t)t*Hq + h0]);
            }
            #pragma unroll
            for (int i = tid; i < 512; i += 256) {
                int h = i >> 3, t0 = (i & 7) * 8;
                uint32_t off = (uint32_t)(h*72 + t0) * 2;
                cp16(ss + AVH + off, &g_vhT[(size_t)h*BT + vb + t0]);
                cp16(ss + AVL + off, &g_vlT[(size_t)h*BT + vb + t0]);
            }
        };

        // Q fragments (fp16 hi, lo) in registers
        uint32_t qh[4][4], ql[4][4];
        {
            const size_t rb0 = (size_t)(b*Tq + q0 + warp*16 + rql) * Hq;
            const size_t rb1 = rb0 + 8*Hq;
            #pragma unroll
            for (int ks = 0; ks < 4; ++ks) {
                int k0 = ks*16 + qc;
                qh[ks][0] = *(const uint32_t*)&g_qh[rb0 + k0];
                qh[ks][1] = *(const uint32_t*)&g_qh[rb1 + k0];
                qh[ks][2] = *(const uint32_t*)&g_qh[rb0 + k0 + 8];
                qh[ks][3] = *(const uint32_t*)&g_qh[rb1 + k0 + 8];
                ql[ks][0] = *(const uint32_t*)&g_ql[rb0 + k0];
                ql[ks][1] = *(const uint32_t*)&g_ql[rb1 + k0];
                ql[ks][2] = *(const uint32_t*)&g_ql[rb0 + k0 + 8];
                ql[ks][3] = *(const uint32_t*)&g_ql[rb1 + k0 + 8];
            }
        }

        float o[8][4];
        #pragma unroll
        for (int nt = 0; nt < 8; ++nt)
            #pragma unroll
            for (int j = 0; j < 4; ++j) o[nt][j] = 0.0f;
        float m0r = -1e30f, m1r = -1e30f, l0r = 0.0f, l1r = 0.0f;

        const int row0g = q0 + warp*16 + rql;

        issueKV(ktbeg, 0);
        CP_COMMIT();
        int stg = 0;

        for (int kt = ktbeg; kt < ktend; ++kt) {
            CP_WAIT(0);
            __syncthreads();
            if (kt + 1 < ktend) { issueKV(kt + 1, stg ^ 1); CP_COMMIT(); }

            const uint32_t ss = sbA + stg*ASTG;

            // ---- S = (Qh + Ql) K^T ----
            float s[8][4];
            #pragma unroll
            for (int nt = 0; nt < 8; ++nt)
                #pragma unroll
                for (int j = 0; j < 4; ++j) s[nt][j] = 0.0f;

            #pragma unroll
            for (int ks = 0; ks < 4; ++ks) {
                #pragma unroll
                for (int ntp = 0; ntp < 4; ++ntp) {
                    uint32_t kf[4];
                    ldsm4(kf, ss + AK + (uint32_t)(ntp*16*72 + ks*16)*2 + bnoff);
                    mma_f16(s[2*ntp],   qh[ks], &kf[0]);
                    mma_f16(s[2*ntp],   ql[ks], &kf[0]);
                    mma_f16(s[2*ntp+1], qh[ks], &kf[2]);
                    mma_f16(s[2*ntp+1], ql[ks], &kf[2]);
                }
            }

            // ---- scale (exp2 domain) + causal mask ----
            const bool need_mask = (kt >= 2*qtile);
            #pragma unroll
            for (int nt = 0; nt < 8; ++nt) {
                const int colg = kt*64 + nt*8 + qc;
                #pragma unroll
                for (int j = 0; j < 4; ++j) {
                    float v = s[nt][j] * SC_LOG2E;
                    if (need_mask) {
                        int cg = colg + (j & 1);
                        int rg = row0g + ((j >> 1) ? 8 : 0);
                        if (cg > rg) v = -1e30f;
                    }
                    s[nt][j] = v;
                }
            }

            // ---- warp-local online softmax (base-2) ----
            float mx0 = -1e30f, mx1 = -1e30f;
            #pragma unroll
            for (int nt = 0; nt < 8; ++nt) {
                mx0 = fmaxf(mx0, fmaxf(s[nt][0], s[nt][1]));
                mx1 = fmaxf(mx1, fmaxf(s[nt][2], s[nt][3]));
            }
            mx0 = fmaxf(mx0, __shfl_xor_sync(0xffffffffu, mx0, 1));
            mx0 = fmaxf(mx0, __shfl_xor_sync(0xffffffffu, mx0, 2));
            mx1 = fmaxf(mx1, __shfl_xor_sync(0xffffffffu, mx1, 1));
            mx1 = fmaxf(mx1, __shfl_xor_sync(0xffffffffu, mx1, 2));
            const float mn0 = fmaxf(m0r, mx0);
            const float mn1 = fmaxf(m1r, mx1);
            const float al0 = ex2(m0r - mn0);
            const float al1 = ex2(m1r - mn1);
            m0r = mn0; m1r = mn1;

            float sum0 = 0.0f, sum1 = 0.0f;
            uint32_t pha[8], phb[8];
            #pragma unroll
            for (int nt = 0; nt < 8; ++nt) {
                float p0 = ex2(s[nt][0] - mn0);
                float p1 = ex2(s[nt][1] - mn0);
                float p2 = ex2(s[nt][2] - mn1);
                float p3 = ex2(s[nt][3] - mn1);
                sum0 += p0 + p1; sum1 += p2 + p3;
                pha[nt] = pack_h2(p0, p1);
                phb[nt] = pack_h2(p2, p3);
            }
            sum0 += __shfl_xor_sync(0xffffffffu, sum0, 1);
            sum0 += __shfl_xor_sync(0xffffffffu, sum0, 2);
            sum1 += __shfl_xor_sync(0xffffffffu, sum1, 1);
            sum1 += __shfl_xor_sync(0xffffffffu, sum1, 2);
            l0r = l0r * al0 + sum0;
            l1r = l1r * al1 + sum1;

            #pragma unroll
            for (int nt = 0; nt < 8; ++nt) {
                o[nt][0] *= al0; o[nt][1] *= al0;
                o[nt][2] *= al1; o[nt][3] *= al1;
            }

            // ---- O += P (Vh + Vl) ----
            #pragma unroll
            for (int ks = 0; ks < 4; ++ks) {
                uint32_t pa[4] = {pha[2*ks], phb[2*ks], pha[2*ks+1], phb[2*ks+1]};
                #pragma unroll
                for (int ntp = 0; ntp < 4; ++ntp) {
                    uint32_t vh[4], vl[4];
                    uint32_t a = ss + AVH + (uint32_t)(ntp*16*72 + ks*16)*2 + bnoff;
                    ldsm4(vh, a);
                    ldsm4(vl, a + (AVL - AVH));
                    mma_f16(o[2*ntp],   pa, &vh[0]);
                    mma_f16(o[2*ntp],   pa, &vl[0]);
                    mma_f16(o[2*ntp+1], pa, &vh[2]);
                    mma_f16(o[2*ntp+1], pa, &vl[2]);
                }
            }

            stg ^= 1;
        }

        // ---- write unnormalized partials ----
        const int rl0 = warp*16 + rql;
        float* po = &g_po[half][bq][0][0];
        #pragma unroll
        for (int nt = 0; nt < 8; ++nt) {
            const int col = nt*8 + qc;
            *(float2*)&po[(size_t)rl0*64 + col]      = make_float2(o[nt][0], o[nt][1]);
            *(float2*)&po[(size_t)(rl0+8)*64 + col]  = make_float2(o[nt][2], o[nt][3]);
        }
        if ((lane & 3) == 0) {
            g_pml[half][bq][rl0]     = make_float2(m0r, l0r);
            g_pml[half][bq][rl0 + 8] = make_float2(m1r, l1r);
        }

        // ---- last finisher merges (base-2 weights) ----
        __threadfence();
        __syncthreads();
        if (tid == 0) s_done = atomicAdd(&g_flag[bq], 1);
        __syncthreads();
        if (s_done == 1) {
            __threadfence();
            const int r  = tid >> 1;
            const int ch = (tid & 1) * 32;
            float2 A  = g_pml[0][bq][r];
            float2 Bv = g_pml[1][bq][r];
            float m  = fmaxf(A.x, Bv.x);
            float wA = ex2(A.x - m);
            float wB = ex2(Bv.x - m);
            float inv = 1.0f / (wA*A.y + wB*Bv.y);
            const float4* pa = (const float4*)&g_po[0][bq][r][ch];
            const float4* pb = (const float4*)&g_po[1][bq][r][ch];
            float4* pw = (float4*)&out[((size_t)(b*Tq + q0 + r))*64 + ch];
            #pragma unroll
            for (int j = 0; j < 8; ++j) {
                float4 a = pa[j], c = pb[j];
                pw[j] = make_float4((wA*a.x + wB*c.x)*inv, (wA*a.y + wB*c.y)*inv,
                                    (wA*a.z + wB*c.z)*inv, (wA*a.w + wB*c.w)*inv);
            }
        }
    }
}

// ---------------------------------------------------------------------------
extern "C" void kernel_launch(void* const* d_in, const int* in_sizes, int n_in,
                              void* d_out, int out_size)
{
    const float* x  = (const float*)d_in[0];
    const float* Wq = (const float*)d_in[1];
    const float* Wk = (const float*)d_in[2];
    const float* Wv = (const float*)d_in[3];
    float* out = (float*)d_out;

    (void)in_sizes; (void)n_in; (void)out_size;

    wsplit_kernel<<<dim3(16, 3), 256>>>(Wq, Wk, Wv);

    cudaFuncSetAttribute(qkv_gemm_kernel,
                         cudaFuncAttributeMaxDynamicSharedMemorySize, QSM_TOTAL);
    qkv_gemm_kernel<<<128, 256, QSM_TOTAL>>>(x);

    cudaFuncSetAttribute(attn_kernel,
                         cudaFuncAttributeMaxDynamicSharedMemorySize, ASM_TOTAL);
    attn_kernel<<<148, 256, ASM_TOTAL>>>(out);
}

// round 10
// speedup vs baseline: 5.9473x; 1.2496x over previous
#include <cuda_runtime.h>
#include <cuda_fp16.h>
#include <cstdint>

#define Bq 8
#define Tq 2048
#define Dq 1024
#define Hq 64
#define BT (Bq*Tq)
#define NQKV 192

// ---------------- device scratch (static globals: allowed) ----------------
__device__ __half g_wf[NQKV*Dq];          // transposed: [n][k], fp16
__device__ __half g_q [BT*Hq];            // [t][h] fp16
__device__ __half g_k [BT*Hq];            // [t][h] fp16
__device__ __half g_vT[Hq*BT];            // [h][t] fp16
__device__ float  g_po[2][128][128][64];
__device__ float2 g_pml[2][128][128];
__device__ int    g_ctr;
__device__ int    g_flag[128];

// ---------------- helpers ----------------
__device__ __forceinline__ void mma_f16(float* c, const uint32_t* a, const uint32_t* b)
{
    asm volatile(
        "mma.sync.aligned.m16n8k16.row.col.f32.f16.f16.f32 "
        "{%0,%1,%2,%3}, {%4,%5,%6,%7}, {%8,%9}, {%0,%1,%2,%3};"
        : "+f"(c[0]), "+f"(c[1]), "+f"(c[2]), "+f"(c[3])
        : "r"(a[0]), "r"(a[1]), "r"(a[2]), "r"(a[3]), "r"(b[0]), "r"(b[1]));
}

__device__ __forceinline__ void ldsm4(uint32_t* r, uint32_t addr)
{
    asm volatile("ldmatrix.sync.aligned.m8n8.x4.shared.b16 {%0,%1,%2,%3}, [%4];"
        : "=r"(r[0]), "=r"(r[1]), "=r"(r[2]), "=r"(r[3]) : "r"(addr));
}

__device__ __forceinline__ float ex2(float x)
{
    float y;
    asm("ex2.approx.f32 %0, %1;" : "=f"(y) : "f"(x));
    return y;
}

__device__ __forceinline__ uint32_t pack_h2(float a, float b)
{
    __half2 t = __floats2half2_rn(a, b);
    return *(uint32_t*)&t;
}

__device__ __forceinline__ uint32_t smem_u32(const void* p) {
    uint32_t a;
    asm("{ .reg .u64 t; cvta.to.shared.u64 t, %1; cvt.u32.u64 %0, t; }"
        : "=r"(a) : "l"(p));
    return a;
}

__device__ __forceinline__ void cp16(uint32_t d, const void* s) {
    asm volatile("cp.async.cg.shared.global [%0], [%1], 16;" :: "r"(d), "l"(s) : "memory");
}
#define CP_COMMIT() asm volatile("cp.async.commit_group;" ::: "memory")
#define CP_WAIT(n)  asm volatile("cp.async.wait_group %0;" :: "n"(n) : "memory")

// ---------------------------------------------------------------------------
// Kernel 0: W -> transposed fp16; resets queue state.
// ---------------------------------------------------------------------------
__global__ __launch_bounds__(256) void wsplit_kernel(
    const float* __restrict__ Wq, const float* __restrict__ Wk, const float* __restrict__ Wv)
{
    __shared__ float S[64][65];
    const int kb  = blockIdx.x;
    const int src = blockIdx.y;
    const int tid = threadIdx.x;

    if (kb == 0 && src == 0) {
        if (tid == 0) g_ctr = 0;
        if (tid < 128) g_flag[tid] = 0;
    }

    const float* W = (src == 0) ? Wq : (src == 1) ? Wk : Wv;

    #pragma unroll
    for (int i = tid; i < 1024; i += 256) {
        int kk = i >> 4, h4 = (i & 15) * 4;
        float4 v = *(const float4*)&W[(size_t)(kb*64 + kk)*64 + h4];
        S[kk][h4] = v.x; S[kk][h4+1] = v.y; S[kk][h4+2] = v.z; S[kk][h4+3] = v.w;
    }
    __syncthreads();

    const int n  = tid >> 2;
    const int kq = (tid & 3) * 16;
    const size_t go = (size_t)(src*64 + n)*Dq + kb*64 + kq;
    #pragma unroll
    for (int j = 0; j < 16; j += 2) {
        *(__half2*)&g_wf[go + j] = __floats2half2_rn(S[kq + j][n], S[kq + j + 1][n]);
    }
}

// ---------------------------------------------------------------------------
// Kernel 1: fused convert + QKV GEMM, plain fp16, double-buffered, ldmatrix.
// grid = 128 M-tiles, 256 threads, warp tile m64 x n48.
// ---------------------------------------------------------------------------
#define QX  0
#define QW  10240
#define QST 25600
#define QSM_TOTAL (2*QST)

__global__ __launch_bounds__(256) void qkv_gemm_kernel(const float* __restrict__ x)
{
    extern __shared__ char smem[];
    const uint32_t sb = smem_u32(smem);

    const int tid  = threadIdx.x;
    const int lane = tid & 31;
    const int warp = tid >> 5;
    const int m0   = blockIdx.x * 128;
    const int wm   = warp & 1;
    const int wn   = warp >> 1;
    const int rql  = lane >> 2;
    const int qc   = (lane & 3) * 2;

    const int arow = (lane & 7) + (((lane >> 3) & 1) << 3);
    const int acol = (lane >> 4) << 3;
    const uint32_t axoff = (uint32_t)(arow*40 + acol) * 2;
    const int brow = (lane & 7) + ((lane >> 4) << 3);
    const int bcol = ((lane >> 3) & 1) << 3;
    const uint32_t bxoff = (uint32_t)(brow*40 + bcol) * 2;

    float c[4][6][4];
    #pragma unroll
    for (int mt = 0; mt < 4; ++mt)
        #pragma unroll
        for (int nt = 0; nt < 6; ++nt)
            #pragma unroll
            for (int j = 0; j < 4; ++j) c[mt][nt][j] = 0.0f;

    float4 xr[4];

    auto loadX = [&](int kc) {
        #pragma unroll
        for (int j = 0; j < 4; ++j) {
            int i = tid + j*256;
            int r = i >> 3, c4 = i & 7;
            xr[j] = *(const float4*)&x[(size_t)(m0 + r)*Dq + kc + c4*4];
        }
    };
    auto stsX = [&](int stg) {
        char* s = smem + stg*QST;
        #pragma unroll
        for (int j = 0; j < 4; ++j) {
            int i = tid + j*256;
            int r = i >> 3, c4 = i & 7;
            float4 v = xr[j];
            int off = (r*40 + c4*4) * 2;
            *(__half2*)(s + QX + off)     = __floats2half2_rn(v.x, v.y);
            *(__half2*)(s + QX + off + 4) = __floats2half2_rn(v.z, v.w);
        }
    };
    auto cpW = [&](int kc, int stg) {
        uint32_t s = sb + stg*QST;
        #pragma unroll
        for (int i = tid; i < 768; i += 256) {
            int r = i >> 2, c16 = (i & 3) * 8;
            uint32_t off = (uint32_t)(r*40 + c16) * 2;
            cp16(s + QW + off, &g_wf[(size_t)r*Dq + kc + c16]);
        }
    };

    loadX(0);
    cpW(0, 0);
    CP_COMMIT();
    stsX(0);
    CP_WAIT(0);
    __syncthreads();

    for (int i = 0; i < 32; ++i) {
        const int cur = i & 1, nxt = cur ^ 1;
        const int kc = i * 32;
        if (i < 31) {
            cpW(kc + 32, nxt);
            CP_COMMIT();
            loadX(kc + 32);
        }

        const uint32_t sc = sb + cur*QST;

        #pragma unroll
        for (int ks = 0; ks < 2; ++ks) {
            const int k0 = ks*16;
            uint32_t ah[4][4];
            #pragma unroll
            for (int mt = 0; mt < 4; ++mt)
                ldsm4(ah[mt], sc + QX + (uint32_t)((wm*64 + mt*16)*40 + k0)*2 + axoff);
            #pragma unroll
            for (int ntp = 0; ntp < 3; ++ntp) {
                uint32_t wf[4];
                ldsm4(wf, sc + QW + (uint32_t)((wn*48 + ntp*16)*40 + k0)*2 + bxoff);
                #pragma unroll
                for (int mt = 0; mt < 4; ++mt) {
                    mma_f16(c[mt][2*ntp],   ah[mt], &wf[0]);
                    mma_f16(c[mt][2*ntp+1], ah[mt], &wf[2]);
                }
            }
        }

        if (i < 31) stsX(nxt);
        CP_WAIT(0);
        __syncthreads();
    }

    // epilogue: fp32 -> fp16 scatter (q, k row-major; v transposed)
    #pragma unroll
    for (int mt = 0; mt < 4; ++mt) {
        #pragma unroll
        for (int nt = 0; nt < 6; ++nt) {
            const int gc = wn*48 + nt*8 + qc;
            #pragma unroll
            for (int hf = 0; hf < 2; ++hf) {
                const int row = m0 + wm*64 + mt*16 + rql + hf*8;
                float v0 = c[mt][nt][hf*2], v1 = c[mt][nt][hf*2 + 1];
                if (gc < 64) {
                    *(__half2*)&g_q[(size_t)row*Hq + gc] = __floats2half2_rn(v0, v1);
                } else if (gc < 128) {
                    *(__half2*)&g_k[(size_t)row*Hq + gc - 64] = __floats2half2_rn(v0, v1);
                } else {
                    const int h = gc - 128;
                    g_vT[(size_t) h   *BT + row] = __float2half_rn(v0);
                    g_vT[(size_t)(h+1)*BT + row] = __float2half_rn(v1);
                }
            }
        }
    }
}

// ---------------------------------------------------------------------------
// Kernel 2: persistent split-K flash attention + fused merge, plain fp16.
// Double-buffered, ldmatrix, exp2 softmax. grid = 148.
// ---------------------------------------------------------------------------
#define NITEMS 256
#define AK  0
#define AV  9216
#define ASTG 18432
#define ASM_TOTAL (2*ASTG)
#define SC_LOG2E 0.1803368801111244f   // 0.125 * log2(e)

__global__ __launch_bounds__(256) void attn_kernel(float* __restrict__ out)
{
    extern __shared__ char asmem[];
    __shared__ int s_item, s_done;

    const uint32_t sbA = smem_u32(asmem);
    const int tid   = threadIdx.x;
    const int lane  = tid & 31;
    const int warp  = tid >> 5;
    const int qc    = (lane & 3) * 2;
    const int rql   = lane >> 2;

    const int brow = (lane & 7) + ((lane >> 4) << 3);
    const int bcol = ((lane >> 3) & 1) << 3;
    const uint32_t bnoff = (uint32_t)(brow*72 + bcol) * 2;

    while (true) {
        __syncthreads();
        if (tid == 0) s_item = atomicAdd(&g_ctr, 1);
        __syncthreads();
        const int item = s_item;
        if (item >= NITEMS) break;

        const int qtile = 15 - (item >> 4);
        const int inner = item & 15;
        const int b     = inner >> 1;
        const int half  = inner & 1;
        const int q0    = qtile * 128;
        const int bq    = b*16 + qtile;

        const int ktbeg = half ? (qtile + 1) : 0;
        const int ktend = half ? (2*qtile + 2) : (qtile + 1);

        auto issueKV = [&](int kt, int stg) {
            const uint32_t ss = sbA + stg*ASTG;
            const size_t kb = (size_t)(b*Tq + kt*64) * Hq;
            const size_t vb = (size_t)(b*Tq + kt*64);
            #pragma unroll
            for (int i = tid; i < 512; i += 256) {
                int t = i >> 3, h0 = (i & 7) * 8;
                cp16(ss + AK + (uint32_t)(t*72 + h0)*2, &g_k[kb + (size_t)t*Hq + h0]);
            }
            #pragma unroll
            for (int i = tid; i < 512; i += 256) {
                int h = i >> 3, t0 = (i & 7) * 8;
                cp16(ss + AV + (uint32_t)(h*72 + t0)*2, &g_vT[(size_t)h*BT + vb + t0]);
            }
        };

        // Q fragments in registers
        uint32_t qf[4][4];
        {
            const size_t rb0 = (size_t)(b*Tq + q0 + warp*16 + rql) * Hq;
            const size_t rb1 = rb0 + 8*Hq;
            #pragma unroll
            for (int ks = 0; ks < 4; ++ks) {
                int k0 = ks*16 + qc;
                qf[ks][0] = *(const uint32_t*)&g_q[rb0 + k0];
                qf[ks][1] = *(const uint32_t*)&g_q[rb1 + k0];
                qf[ks][2] = *(const uint32_t*)&g_q[rb0 + k0 + 8];
                qf[ks][3] = *(const uint32_t*)&g_q[rb1 + k0 + 8];
            }
        }

        float o[8][4];
        #pragma unroll
        for (int nt = 0; nt < 8; ++nt)
            #pragma unroll
            for (int j = 0; j < 4; ++j) o[nt][j] = 0.0f;
        float m0r = -1e30f, m1r = -1e30f, l0r = 0.0f, l1r = 0.0f;

        const int row0g = q0 + warp*16 + rql;

        issueKV(ktbeg, 0);
        CP_COMMIT();
        int stg = 0;

        for (int kt = ktbeg; kt < ktend; ++kt) {
            CP_WAIT(0);
            __syncthreads();
            if (kt + 1 < ktend) { issueKV(kt + 1, stg ^ 1); CP_COMMIT(); }

            const uint32_t ss = sbA + stg*ASTG;

            // ---- S = Q K^T ----
            float s[8][4];
            #pragma unroll
            for (int nt = 0; nt < 8; ++nt)
                #pragma unroll
                for (int j = 0; j < 4; ++j) s[nt][j] = 0.0f;

            #pragma unroll
            for (int ks = 0; ks < 4; ++ks) {
                #pragma unroll
                for (int ntp = 0; ntp < 4; ++ntp) {
                    uint32_t kf[4];
                    ldsm4(kf, ss + AK + (uint32_t)(ntp*16*72 + ks*16)*2 + bnoff);
                    mma_f16(s[2*ntp],   qf[ks], &kf[0]);
                    mma_f16(s[2*ntp+1], qf[ks], &kf[2]);
                }
            }

            // ---- scale (exp2 domain) + causal mask ----
            const bool need_mask = (kt >= 2*qtile);
            #pragma unroll
            for (int nt = 0; nt < 8; ++nt) {
                const int colg = kt*64 + nt*8 + qc;
                #pragma unroll
                for (int j = 0; j < 4; ++j) {
                    float v = s[nt][j] * SC_LOG2E;
                    if (need_mask) {
                        int cg = colg + (j & 1);
                        int rg = row0g + ((j >> 1) ? 8 : 0);
                        if (cg > rg) v = -1e30f;
                    }
                    s[nt][j] = v;
                }
            }

            // ---- warp-local online softmax (base-2) ----
            float mx0 = -1e30f, mx1 = -1e30f;
            #pragma unroll
            for (int nt = 0; nt < 8; ++nt) {
                mx0 = fmaxf(mx0, fmaxf(s[nt][0], s[nt][1]));
                mx1 = fmaxf(mx1, fmaxf(s[nt][2], s[nt][3]));
            }
            mx0 = fmaxf(mx0, __shfl_xor_sync(0xffffffffu, mx0, 1));
            mx0 = fmaxf(mx0, __shfl_xor_sync(0xffffffffu, mx0, 2));
            mx1 = fmaxf(mx1, __shfl_xor_sync(0xffffffffu, mx1, 1));
            mx1 = fmaxf(mx1, __shfl_xor_sync(0xffffffffu, mx1, 2));
            const float mn0 = fmaxf(m0r, mx0);
            const float mn1 = fmaxf(m1r, mx1);
            const float al0 = ex2(m0r - mn0);
            const float al1 = ex2(m1r - mn1);
            m0r = mn0; m1r = mn1;

            float sum0 = 0.0f, sum1 = 0.0f;
            uint32_t pha[8], phb[8];
            #pragma unroll
            for (int nt = 0; nt < 8; ++nt) {
                float p0 = ex2(s[nt][0] - mn0);
                float p1 = ex2(s[nt][1] - mn0);
                float p2 = ex2(s[nt][2] - mn1);
                float p3 = ex2(s[nt][3] - mn1);
                sum0 += p0 + p1; sum1 += p2 + p3;
                pha[nt] = pack_h2(p0, p1);
                phb[nt] = pack_h2(p2, p3);
            }
            sum0 += __shfl_xor_sync(0xffffffffu, sum0, 1);
            sum0 += __shfl_xor_sync(0xffffffffu, sum0, 2);
            sum1 += __shfl_xor_sync(0xffffffffu, sum1, 1);
            sum1 += __shfl_xor_sync(0xffffffffu, sum1, 2);
            l0r = l0r * al0 + sum0;
            l1r = l1r * al1 + sum1;

            #pragma unroll
            for (int nt = 0; nt < 8; ++nt) {
                o[nt][0] *= al0; o[nt][1] *= al0;
                o[nt][2] *= al1; o[nt][3] *= al1;
            }

            // ---- O += P V ----
            #pragma unroll
            for (int ks = 0; ks < 4; ++ks) {
                uint32_t pa[4] = {pha[2*ks], phb[2*ks], pha[2*ks+1], phb[2*ks+1]};
                #pragma unroll
                for (int ntp = 0; ntp < 4; ++ntp) {
                    uint32_t vf[4];
                    ldsm4(vf, ss + AV + (uint32_t)(ntp*16*72 + ks*16)*2 + bnoff);
                    mma_f16(o[2*ntp],   pa, &vf[0]);
                    mma_f16(o[2*ntp+1], pa, &vf[2]);
                }
            }

            stg ^= 1;
        }

        // ---- write unnormalized partials ----
        const int rl0 = warp*16 + rql;
        float* po = &g_po[half][bq][0][0];
        #pragma unroll
        for (int nt = 0; nt < 8; ++nt) {
            const int col = nt*8 + qc;
            *(float2*)&po[(size_t)rl0*64 + col]      = make_float2(o[nt][0], o[nt][1]);
            *(float2*)&po[(size_t)(rl0+8)*64 + col]  = make_float2(o[nt][2], o[nt][3]);
        }
        if ((lane & 3) == 0) {
            g_pml[half][bq][rl0]     = make_float2(m0r, l0r);
            g_pml[half][bq][rl0 + 8] = make_float2(m1r, l1r);
        }

        // ---- last finisher merges (base-2 weights) ----
        __threadfence();
        __syncthreads();
        if (tid == 0) s_done = atomicAdd(&g_flag[bq], 1);
        __syncthreads();
        if (s_done == 1) {
            __threadfence();
            const int r  = tid >> 1;
            const int ch = (tid & 1) * 32;
            float2 A  = g_pml[0][bq][r];
            float2 Bv = g_pml[1][bq][r];
            float m  = fmaxf(A.x, Bv.x);
            float wA = ex2(A.x - m);
            float wB = ex2(Bv.x - m);
            float inv = 1.0f / (wA*A.y + wB*Bv.y);
            const float4* pa = (const float4*)&g_po[0][bq][r][ch];
            const float4* pb = (const float4*)&g_po[1][bq][r][ch];
            float4* pw = (float4*)&out[((size_t)(b*Tq + q0 + r))*64 + ch];
            #pragma unroll
            for (int j = 0; j < 8; ++j) {
                float4 a = pa[j], c = pb[j];
                pw[j] = make_float4((wA*a.x + wB*c.x)*inv, (wA*a.y + wB*c.y)*inv,
                                    (wA*a.z + wB*c.z)*inv, (wA*a.w + wB*c.w)*inv);
            }
        }
    }
}

// ---------------------------------------------------------------------------
extern "C" void kernel_launch(void* const* d_in, const int* in_sizes, int n_in,
                              void* d_out, int out_size)
{
    const float* x  = (const float*)d_in[0];
    const float* Wq = (const float*)d_in[1];
    const float* Wk = (const float*)d_in[2];
    const float* Wv = (const float*)d_in[3];
    float* out = (float*)d_out;

    (void)in_sizes; (void)n_in; (void)out_size;

    wsplit_kernel<<<dim3(16, 3), 256>>>(Wq, Wk, Wv);

    cudaFuncSetAttribute(qkv_gemm_kernel,
                         cudaFuncAttributeMaxDynamicSharedMemorySize, QSM_TOTAL);
    qkv_gemm_kernel<<<128, 256, QSM_TOTAL>>>(x);

    cudaFuncSetAttribute(attn_kernel,
                         cudaFuncAttributeMaxDynamicSharedMemorySize, ASM_TOTAL);
    attn_kernel<<<148, 256, ASM_TOTAL>>>(out);
}